// round 1
// baseline (speedup 1.0000x reference)
#include <cuda_runtime.h>
#include <math.h>

// ---------------------------------------------------------------------------
// DTHyperNet: B=8192, F=H=512, C=100, D=4 -> NODES=15, LEAVES=16, NBLOCKS=2
// Pipeline:
//   h  = relu(bn(x@w_in + b_in))
//   2x residual blocks: o=gelu(bn(h@bw1+bb1)); o=gelu(bn(o@bw2+bb2)); h=o+h
//   fi = h@w_fi+b_fi  [B,15,512];  fs = h@w_fs+b_fs;  lnc = h@w_lc+b_lc [B,16,100]
//   sfi = softmax(fi,-1); node_sd = sigmoid(dot(sfi,x) - dot(sfi,fs))   [B,15]
//   tree-route -> coeff [B,16]; out = coeff @ lnc                       [B,100]
// ---------------------------------------------------------------------------

#define BQ   8192
#define FF   512
#define HH   512
#define CC   100
#define NNODES 15
#define NLEAVES 16
#define EPSV 1e-5f

// scratch (device globals: no allocations allowed)
__device__ float g_h0[BQ * HH];
__device__ float g_h1[BQ * HH];
__device__ float g_t [BQ * HH];
__device__ float g_fi[BQ * NNODES * FF];
__device__ float g_fs[BQ * NNODES * FF];
__device__ float g_lc[BQ * NLEAVES * CC];
__device__ float g_sd[BQ * NNODES];

// ---------------------------------------------------------------------------
// Tiled SGEMM:  C[M,N] = A[M,K] @ B[K,N]  + fused epilogue
//   EPI 0: out = acc + bias[col]
//   EPI 1: out = relu((acc+bias)*gamma*rs + beta)
//   EPI 2: out = gelu((acc+bias)*gamma*rs + beta)
//   EPI 3: out = gelu((acc+bias)*gamma*rs + beta) + resid[row,col]
// 128x128 block tile, BK=8, 256 threads, 8x8 per-thread register tile.
// M, K assumed multiples of 128/8; N only assumed multiple of 4.
// ---------------------------------------------------------------------------
#define BM 128
#define BN 128
#define BK 8
#define TM 8
#define TN 8

template <int EPI>
__global__ __launch_bounds__(256) void sgemm_kernel(
    const float* __restrict__ A, const float* __restrict__ B,
    float* __restrict__ C, int M, int N, int K,
    const float* __restrict__ bias, const float* __restrict__ gamma,
    const float* __restrict__ beta, const float* __restrict__ resid)
{
    __shared__ float As[BK][BM];
    __shared__ float Bs[BK][BN];

    const int tid = threadIdx.x;
    const int bm  = blockIdx.y * BM;
    const int bn  = blockIdx.x * BN;
    const int tx  = tid & 15;     // 16 cols of threads
    const int ty  = tid >> 4;     // 16 rows of threads

    const int aRow = tid >> 1;          // 0..127
    const int aCol = (tid & 1) << 2;    // 0 or 4
    const int bRow = tid >> 5;          // 0..7
    const int bCol = (tid & 31) << 2;   // 0..124

    float acc[TM][TN];
#pragma unroll
    for (int i = 0; i < TM; i++)
#pragma unroll
        for (int j = 0; j < TN; j++) acc[i][j] = 0.0f;

    const float* Aptr = A + (size_t)(bm + aRow) * K + aCol;
    const bool bColOK = (bn + bCol) < N;

    for (int k0 = 0; k0 < K; k0 += BK) {
        float4 a4 = *(const float4*)(Aptr + k0);
        As[aCol + 0][aRow] = a4.x;
        As[aCol + 1][aRow] = a4.y;
        As[aCol + 2][aRow] = a4.z;
        As[aCol + 3][aRow] = a4.w;

        float4 b4 = make_float4(0.f, 0.f, 0.f, 0.f);
        if (bColOK)
            b4 = *(const float4*)(B + (size_t)(k0 + bRow) * N + bn + bCol);
        *(float4*)&Bs[bRow][bCol] = b4;

        __syncthreads();
#pragma unroll
        for (int kk = 0; kk < BK; kk++) {
            float a[TM], b[TN];
#pragma unroll
            for (int i = 0; i < TM; i++) a[i] = As[kk][ty * TM + i];
#pragma unroll
            for (int j = 0; j < TN; j++) b[j] = Bs[kk][tx * TN + j];
#pragma unroll
            for (int i = 0; i < TM; i++)
#pragma unroll
                for (int j = 0; j < TN; j++)
                    acc[i][j] = fmaf(a[i], b[j], acc[i][j]);
        }
        __syncthreads();
    }

    // -------- epilogue --------
    const float RS = rsqrtf(1.0f + EPSV);
    const int row0 = bm + ty * TM;
    const int col0 = bn + tx * TN;

    float bj[TN], sj[TN], bej[TN];
#pragma unroll
    for (int j = 0; j < TN; j++) {
        int c = col0 + j;
        bool ok = c < N;
        bj[j] = ok ? bias[c] : 0.0f;
        if (EPI >= 1) {
            sj[j]  = ok ? gamma[c] * RS : 0.0f;
            bej[j] = ok ? beta[c] : 0.0f;
        } else {
            sj[j] = 0.0f; bej[j] = 0.0f;
        }
    }

#pragma unroll
    for (int i = 0; i < TM; i++) {
        int r = row0 + i;
#pragma unroll
        for (int jv = 0; jv < TN; jv += 4) {
            int c = col0 + jv;
            if (c >= N) continue;
            float v[4];
#pragma unroll
            for (int u = 0; u < 4; u++) {
                float t = acc[i][jv + u] + bj[jv + u];
                if (EPI >= 1) t = t * sj[jv + u] + bej[jv + u];
                if (EPI == 1) t = fmaxf(t, 0.0f);
                if (EPI >= 2) t = 0.5f * t * (1.0f + erff(t * 0.70710678118654752f));
                v[u] = t;
            }
            if (EPI == 3) {
                float4 rv = *(const float4*)(resid + (size_t)r * N + c);
                v[0] += rv.x; v[1] += rv.y; v[2] += rv.z; v[3] += rv.w;
            }
            float4 o; o.x = v[0]; o.y = v[1]; o.z = v[2]; o.w = v[3];
            *(float4*)(C + (size_t)r * N + c) = o;
        }
    }
}

// ---------------------------------------------------------------------------
// Per-row node reduction: for each (b, n):
//   m  = max_f fi[b,n,f]
//   e  = exp(fi - m);  se = sum e;  sx = sum e*x[b,f];  sf = sum e*fs[b,n,f]
//   sd[b,n] = sigmoid((sx - sf)/se)
// One block (256 thr) per batch row; loops over the 15 nodes.
// ---------------------------------------------------------------------------
__global__ __launch_bounds__(256) void node_sd_kernel(
    const float* __restrict__ fi, const float* __restrict__ fs,
    const float* __restrict__ x, float* __restrict__ sd)
{
    __shared__ float xs[FF];
    __shared__ float red[32];
    const int b = blockIdx.x;
    const int tid = threadIdx.x;
    const int lane = tid & 31;
    const int warp = tid >> 5;

    xs[tid]       = x[(size_t)b * FF + tid];
    xs[tid + 256] = x[(size_t)b * FF + tid + 256];
    __syncthreads();

    const float xv0 = xs[tid];
    const float xv1 = xs[tid + 256];
    const float* fib = fi + (size_t)b * (NNODES * FF);
    const float* fsb = fs + (size_t)b * (NNODES * FF);

    for (int n = 0; n < NNODES; n++) {
        const float a0 = fib[n * FF + tid];
        const float a1 = fib[n * FF + tid + 256];

        // block max
        float m = fmaxf(a0, a1);
#pragma unroll
        for (int o = 16; o > 0; o >>= 1)
            m = fmaxf(m, __shfl_xor_sync(0xffffffffu, m, o));
        if (lane == 0) red[warp] = m;
        __syncthreads();
        if (warp == 0) {
            float mm = red[lane & 7];
#pragma unroll
            for (int o = 4; o > 0; o >>= 1)
                mm = fmaxf(mm, __shfl_xor_sync(0xffffffffu, mm, o));
            if (lane == 0) red[0] = mm;
        }
        __syncthreads();
        m = red[0];
        __syncthreads();   // everyone has read red[0] before it is overwritten

        const float e0 = __expf(a0 - m);
        const float e1 = __expf(a1 - m);
        float se = e0 + e1;
        float sx = e0 * xv0 + e1 * xv1;
        const float f0 = fsb[n * FF + tid];
        const float f1 = fsb[n * FF + tid + 256];
        float sf = e0 * f0 + e1 * f1;

#pragma unroll
        for (int o = 16; o > 0; o >>= 1) {
            se += __shfl_xor_sync(0xffffffffu, se, o);
            sx += __shfl_xor_sync(0xffffffffu, sx, o);
            sf += __shfl_xor_sync(0xffffffffu, sf, o);
        }
        if (lane == 0) { red[warp] = se; red[8 + warp] = sx; red[16 + warp] = sf; }
        __syncthreads();
        if (tid == 0) {
            float SE = 0.f, SX = 0.f, SF = 0.f;
#pragma unroll
            for (int w = 0; w < 8; w++) { SE += red[w]; SX += red[8 + w]; SF += red[16 + w]; }
            float z = (SX - SF) / SE;
            sd[b * NNODES + n] = 1.0f / (1.0f + expf(-z));
        }
        __syncthreads();
    }
}

// ---------------------------------------------------------------------------
// Tree combine: coeff[l] = prod over depth of (side? 1-p : p), out = coeff@lnc
// For D=4:  node path per leaf l: {0, 1+(l>>3), 3+(l>>2), 7+(l>>1)}
//           sides:               {(l>>3)&1, (l>>2)&1, (l>>1)&1, l&1}
// ---------------------------------------------------------------------------
__global__ __launch_bounds__(128) void combine_kernel(
    const float* __restrict__ sd, const float* __restrict__ lnc,
    float* __restrict__ out)
{
    __shared__ float s[NNODES];
    __shared__ float coeff[NLEAVES];
    const int b = blockIdx.x;
    const int tid = threadIdx.x;

    if (tid < NNODES) s[tid] = sd[b * NNODES + tid];
    __syncthreads();
    if (tid < NLEAVES) {
        const int l = tid;
        float p, c;
        p = s[0];            c  = ((l >> 3) & 1) ? 1.0f - p : p;
        p = s[1 + (l >> 3)]; c *= ((l >> 2) & 1) ? 1.0f - p : p;
        p = s[3 + (l >> 2)]; c *= ((l >> 1) & 1) ? 1.0f - p : p;
        p = s[7 + (l >> 1)]; c *= (l & 1)        ? 1.0f - p : p;
        coeff[l] = c;
    }
    __syncthreads();
    if (tid < CC) {
        const float* lp = lnc + (size_t)b * (NLEAVES * CC) + tid;
        float acc = 0.0f;
#pragma unroll
        for (int l = 0; l < NLEAVES; l++) acc += coeff[l] * lp[l * CC];
        out[b * CC + tid] = acc;
    }
}

// ---------------------------------------------------------------------------
extern "C" void kernel_launch(void* const* d_in, const int* in_sizes, int n_in,
                              void* d_out, int out_size)
{
    const float* x    = (const float*)d_in[0];
    const float* w_in = (const float*)d_in[1];
    const float* b_in = (const float*)d_in[2];
    const float* g0   = (const float*)d_in[3];
    const float* be0  = (const float*)d_in[4];
    const float* bw1  = (const float*)d_in[5];
    const float* bb1  = (const float*)d_in[6];
    const float* bg1  = (const float*)d_in[7];
    const float* bbe1 = (const float*)d_in[8];
    const float* bw2  = (const float*)d_in[9];
    const float* bb2  = (const float*)d_in[10];
    const float* bg2  = (const float*)d_in[11];
    const float* bbe2 = (const float*)d_in[12];
    const float* w_fi = (const float*)d_in[13];
    const float* b_fi = (const float*)d_in[14];
    const float* w_fs = (const float*)d_in[15];
    const float* b_fs = (const float*)d_in[16];
    const float* w_lc = (const float*)d_in[17];
    const float* b_lc = (const float*)d_in[18];
    float* out = (float*)d_out;

    float *h0, *h1, *t, *fi, *fs, *lc, *sdp;
    cudaGetSymbolAddress((void**)&h0,  g_h0);
    cudaGetSymbolAddress((void**)&h1,  g_h1);
    cudaGetSymbolAddress((void**)&t,   g_t);
    cudaGetSymbolAddress((void**)&fi,  g_fi);
    cudaGetSymbolAddress((void**)&fs,  g_fs);
    cudaGetSymbolAddress((void**)&lc,  g_lc);
    cudaGetSymbolAddress((void**)&sdp, g_sd);

    const dim3 blk(256);
    const dim3 g512(HH / BN, BQ / BM);                 // (4, 64)
    const dim3 g7680((NNODES * FF + BN - 1) / BN, BQ / BM);   // (60, 64)
    const dim3 g1600((NLEAVES * CC + BN - 1) / BN, BQ / BM);  // (13, 64)

    // trunk
    sgemm_kernel<1><<<g512, blk>>>(x, w_in, h0, BQ, HH, FF, b_in, g0, be0, nullptr);
    // block 0
    sgemm_kernel<2><<<g512, blk>>>(h0, bw1, t, BQ, HH, HH, bb1, bg1, bbe1, nullptr);
    sgemm_kernel<3><<<g512, blk>>>(t, bw2, h1, BQ, HH, HH, bb2, bg2, bbe2, h0);
    // block 1
    sgemm_kernel<2><<<g512, blk>>>(h1, bw1 + HH * HH, t, BQ, HH, HH,
                                   bb1 + HH, bg1 + HH, bbe1 + HH, nullptr);
    sgemm_kernel<3><<<g512, blk>>>(t, bw2 + HH * HH, h0, BQ, HH, HH,
                                   bb2 + HH, bg2 + HH, bbe2 + HH, h1);
    // heads (h lives in h0 now)
    sgemm_kernel<0><<<g7680, blk>>>(h0, w_fi, fi, BQ, NNODES * FF, HH,
                                    b_fi, nullptr, nullptr, nullptr);
    sgemm_kernel<0><<<g7680, blk>>>(h0, w_fs, fs, BQ, NNODES * FF, HH,
                                    b_fs, nullptr, nullptr, nullptr);
    sgemm_kernel<0><<<g1600, blk>>>(h0, w_lc, lc, BQ, NLEAVES * CC, HH,
                                    b_lc, nullptr, nullptr, nullptr);
    // reductions
    node_sd_kernel<<<BQ, 256>>>(fi, fs, x, sdp);
    combine_kernel<<<BQ, 128>>>(sdp, lc, out);
}

// round 3
// speedup vs baseline: 2.1387x; 2.1387x over previous
#include <cuda_runtime.h>
#include <cuda_bf16.h>
#include <cstdint>
#include <math.h>

// ===========================================================================
// DTHyperNet via sm_80-compatible tensor cores (mma.sync bf16, fp32 accum)
// All GEMMs computed as D = Ah*Bh + Ah*Bl + Al*Bh  (2-way bf16 split of fp32)
// expressed as a single GEMM over virtual K = 3*512 = 1536.
// ===========================================================================

#define BQ 8192
#define FF 512
#define HH 512
#define CC 100
#define NNODES 15
#define NLEAVES 16
#define NFI 7680
#define NLC 1600
#define NLCP 1664
#define KDIM 512
#define EPSV 1e-5f

// -------------------- device scratch (no allocations allowed) --------------
__device__ __nv_bfloat16 g_xh[BQ * FF], g_xl[BQ * FF];
__device__ __nv_bfloat16 g_p0h[BQ * HH], g_p0l[BQ * HH];
__device__ __nv_bfloat16 g_p1h[BQ * HH], g_p1l[BQ * HH];
__device__ __nv_bfloat16 g_pth[BQ * HH], g_ptl[BQ * HH];
__device__ __nv_bfloat16 g_wih[HH * HH], g_wil[HH * HH];
__device__ __nv_bfloat16 g_w1h[2 * HH * HH], g_w1l[2 * HH * HH];
__device__ __nv_bfloat16 g_w2h[2 * HH * HH], g_w2l[2 * HH * HH];
__device__ __nv_bfloat16 g_wfih[NFI * HH], g_wfil[NFI * HH];
__device__ __nv_bfloat16 g_wfsh[NFI * HH], g_wfsl[NFI * HH];
__device__ __nv_bfloat16 g_wlch[NLCP * HH], g_wlcl[NLCP * HH];
__device__ float g_fi[(size_t)BQ * NFI];
__device__ float g_fs[(size_t)BQ * NFI];
__device__ float g_lc[(size_t)BQ * NLC];
__device__ float g_sd[BQ * NNODES];

// -------------------- PTX helpers (sm_80 baseline only) --------------------
__device__ __forceinline__ uint32_t smem_u32(const void* p) {
    uint32_t a;
    asm("{ .reg .u64 t; cvta.to.shared.u64 t, %1; cvt.u32.u64 %0, t; }"
        : "=r"(a) : "l"(p));
    return a;
}
#define CP16(dst, src) \
    asm volatile("cp.async.cg.shared.global [%0], [%1], 16;" :: "r"(dst), "l"(src))
#define CP_COMMIT() asm volatile("cp.async.commit_group;" ::: "memory")
#define CP_WAIT0() asm volatile("cp.async.wait_group 0;" ::: "memory")
#define CP_WAIT1() asm volatile("cp.async.wait_group 1;" ::: "memory")

__device__ __forceinline__ void ldsm4(uint32_t* r, uint32_t addr) {
    asm volatile("ldmatrix.sync.aligned.m8n8.x4.shared.b16 {%0,%1,%2,%3}, [%4];"
                 : "=r"(r[0]), "=r"(r[1]), "=r"(r[2]), "=r"(r[3]) : "r"(addr));
}
__device__ __forceinline__ void mma16816(float* c, const uint32_t* a,
                                         uint32_t b0, uint32_t b1) {
    asm volatile(
        "mma.sync.aligned.m16n8k16.row.col.f32.bf16.bf16.f32 "
        "{%0,%1,%2,%3}, {%4,%5,%6,%7}, {%8,%9}, {%0,%1,%2,%3};"
        : "+f"(c[0]), "+f"(c[1]), "+f"(c[2]), "+f"(c[3])
        : "r"(a[0]), "r"(a[1]), "r"(a[2]), "r"(a[3]), "r"(b0), "r"(b1));
}

// smem tile: 128 rows x 32 bf16, padded row stride 80 bytes (conflict-free)
#define ROWB 80
#define TILEB (128 * ROWB)          // 10240
#define STAGEB (2 * TILEB)          // A + B per stage
#define NSTAGE 3
#define SMEM_BYTES (NSTAGE * STAGEB)   // 61440
#define KSTAGES 48                  // 1536 / 32

// ===========================================================================
// GEMM: C[M,N] = sum_p Apart[p][M,512] @ Bpart[p][N,512]^T + epilogue
// parts: (Ah,Bh), (Ah,Bl), (Al,Bh)
// EPI 0: +bias -> fp32    1: bn+relu -> split bf16    2: bn+gelu -> split
// EPI 3: bn+gelu+residual -> split
// grid (Npad/128, BQ/128), 256 threads (8 warps, 2x4, 64x32 warp tiles)
// ===========================================================================
template <int EPI, int F32OUT>
__global__ __launch_bounds__(256) void gemm_mma(
    const __nv_bfloat16* __restrict__ Ah, const __nv_bfloat16* __restrict__ Al,
    const __nv_bfloat16* __restrict__ Bh, const __nv_bfloat16* __restrict__ Bl,
    float* __restrict__ Cf, __nv_bfloat16* __restrict__ Ch, __nv_bfloat16* __restrict__ Cl,
    int Nout,
    const float* __restrict__ bias, const float* __restrict__ gamma,
    const float* __restrict__ beta,
    const __nv_bfloat16* __restrict__ Rh, const __nv_bfloat16* __restrict__ Rl)
{
    extern __shared__ char dsm[];
    const uint32_t sb = smem_u32(dsm);

    const int tid = threadIdx.x;
    const int lane = tid & 31;
    const int wid = tid >> 5;
    const int warp_m = wid >> 2;     // 0..1
    const int warp_n = wid & 3;      // 0..3
    const int bm = blockIdx.y * 128;
    const int bn = blockIdx.x * 128;

    const char* Aparts[3] = { (const char*)Ah + (size_t)bm * 1024,
                              (const char*)Ah + (size_t)bm * 1024,
                              (const char*)Al + (size_t)bm * 1024 };
    const char* Bparts[3] = { (const char*)Bh + (size_t)bn * 1024,
                              (const char*)Bl + (size_t)bn * 1024,
                              (const char*)Bh + (size_t)bn * 1024 };

    // per-thread load slots: 512 chunks A + 512 chunks B per stage
    const int lr0 = tid >> 2;            // A rows for idx=tid, +256
    const int lc0 = (tid & 3) * 16;
    // ldmatrix lane geometry
    const int arow = (lane & 7) + ((lane >> 3) & 1) * 8;
    const int asel = lane >> 4;                      // chunk add (0/1)
    const int brow = ((lane >> 4) & 1) * 8 + (lane & 7);
    const int bsel = (lane >> 3) & 1;
    const uint32_t a_lane = (uint32_t)(warp_m * 64 + arow) * ROWB;
    const uint32_t b_lane = (uint32_t)(warp_n * 32 + brow) * ROWB;

    float acc[4][4][4];
#pragma unroll
    for (int i = 0; i < 4; i++)
#pragma unroll
        for (int j = 0; j < 4; j++)
#pragma unroll
            for (int u = 0; u < 4; u++) acc[i][j][u] = 0.0f;

    auto load_stage = [&](int s, int buf) {
        const int p = s >> 4;
        const int ko = (s & 15) * 64;     // byte offset in 1024B row
        const uint32_t ab = sb + buf * STAGEB;
        const uint32_t bb = ab + TILEB;
        const char* As = Aparts[p] + ko;
        const char* Bs = Bparts[p] + ko;
#pragma unroll
        for (int i = 0; i < 2; i++) {
            const int r = lr0 + i * 64;
            CP16(ab + r * ROWB + lc0, As + (size_t)r * 1024 + lc0);
        }
#pragma unroll
        for (int i = 0; i < 2; i++) {
            const int r = lr0 + i * 64;
            CP16(bb + r * ROWB + lc0, Bs + (size_t)r * 1024 + lc0);
        }
    };

    load_stage(0, 0); CP_COMMIT();
    load_stage(1, 1); CP_COMMIT();

    int buf = 0;
    for (int s = 0; s < KSTAGES; s++) {
        if (s + 2 < KSTAGES) { CP_WAIT1(); } else { CP_WAIT0(); }
        __syncthreads();

        if (s + 2 < KSTAGES) {
            int nb = buf + 2; if (nb >= NSTAGE) nb -= NSTAGE;
            load_stage(s + 2, nb);
            CP_COMMIT();
        }

        const uint32_t ab = sb + buf * STAGEB;
        const uint32_t bb = ab + TILEB;
#pragma unroll
        for (int kh = 0; kh < 2; kh++) {
            uint32_t af[4][4], bf[2][4];
            const uint32_t kadd = (kh * 2) * 16;
#pragma unroll
            for (int m = 0; m < 4; m++)
                ldsm4(af[m], ab + a_lane + m * (16 * ROWB) + kadd + asel * 16);
#pragma unroll
            for (int n2 = 0; n2 < 2; n2++)
                ldsm4(bf[n2], bb + b_lane + n2 * (16 * ROWB) + kadd + bsel * 16);
#pragma unroll
            for (int m = 0; m < 4; m++) {
#pragma unroll
                for (int n = 0; n < 4; n++) {
                    const uint32_t b0 = bf[n >> 1][(n & 1) * 2 + 0];
                    const uint32_t b1 = bf[n >> 1][(n & 1) * 2 + 1];
                    mma16816(acc[m][n], af[m], b0, b1);
                }
            }
        }
        buf++; if (buf == NSTAGE) buf = 0;
    }

    // -------- epilogue --------
    const float RS = rsqrtf(1.0f + EPSV);
    const int lm = lane >> 2;
    const int ln2 = (lane & 3) * 2;
    const int row0 = bm + warp_m * 64;
    const int col0 = bn + warp_n * 32;

#pragma unroll
    for (int m = 0; m < 4; m++) {
#pragma unroll
        for (int n = 0; n < 4; n++) {
            const int gn = col0 + n * 8 + ln2;
            const int r_lo = row0 + m * 16 + lm;
            const int r_hi = r_lo + 8;
            float* c = acc[m][n];
            if (F32OUT) {
                if (gn < Nout) {
                    const float bz0 = bias[gn], bz1 = bias[gn + 1];
                    float2 v0 = make_float2(c[0] + bz0, c[1] + bz1);
                    float2 v1 = make_float2(c[2] + bz0, c[3] + bz1);
                    *(float2*)(Cf + (size_t)r_lo * Nout + gn) = v0;
                    *(float2*)(Cf + (size_t)r_hi * Nout + gn) = v1;
                }
            } else {
                const float bz0 = bias[gn], bz1 = bias[gn + 1];
                const float s0 = gamma[gn] * RS, s1 = gamma[gn + 1] * RS;
                const float e0 = beta[gn], e1 = beta[gn + 1];
                float v[4];
                v[0] = c[0] * 1.0f + bz0; v[1] = c[1] + bz1;
                v[2] = c[2] + bz0;        v[3] = c[3] + bz1;
                v[0] = v[0] * s0 + e0; v[1] = v[1] * s1 + e1;
                v[2] = v[2] * s0 + e0; v[3] = v[3] * s1 + e1;
#pragma unroll
                for (int u = 0; u < 4; u++) {
                    if (EPI == 1) v[u] = fmaxf(v[u], 0.0f);
                    else v[u] = 0.5f * v[u] * (1.0f + erff(v[u] * 0.70710678118654752f));
                }
                if (EPI == 3) {
                    const size_t o0 = (size_t)r_lo * HH + gn;
                    const size_t o1 = (size_t)r_hi * HH + gn;
                    __nv_bfloat162 rh0 = *(const __nv_bfloat162*)(Rh + o0);
                    __nv_bfloat162 rl0 = *(const __nv_bfloat162*)(Rl + o0);
                    __nv_bfloat162 rh1 = *(const __nv_bfloat162*)(Rh + o1);
                    __nv_bfloat162 rl1 = *(const __nv_bfloat162*)(Rl + o1);
                    v[0] += __bfloat162float(rh0.x) + __bfloat162float(rl0.x);
                    v[1] += __bfloat162float(rh0.y) + __bfloat162float(rl0.y);
                    v[2] += __bfloat162float(rh1.x) + __bfloat162float(rl1.x);
                    v[3] += __bfloat162float(rh1.y) + __bfloat162float(rl1.y);
                }
                __nv_bfloat162 hp0, lp0, hp1, lp1;
                hp0.x = __float2bfloat16(v[0]); hp0.y = __float2bfloat16(v[1]);
                lp0.x = __float2bfloat16(v[0] - __bfloat162float(hp0.x));
                lp0.y = __float2bfloat16(v[1] - __bfloat162float(hp0.y));
                hp1.x = __float2bfloat16(v[2]); hp1.y = __float2bfloat16(v[3]);
                lp1.x = __float2bfloat16(v[2] - __bfloat162float(hp1.x));
                lp1.y = __float2bfloat16(v[3] - __bfloat162float(hp1.y));
                *(__nv_bfloat162*)(Ch + (size_t)r_lo * HH + gn) = hp0;
                *(__nv_bfloat162*)(Cl + (size_t)r_lo * HH + gn) = lp0;
                *(__nv_bfloat162*)(Ch + (size_t)r_hi * HH + gn) = hp1;
                *(__nv_bfloat162*)(Cl + (size_t)r_hi * HH + gn) = lp1;
            }
        }
    }
}

// ---------------- split x into bf16 hi/lo -----------------------------------
__global__ __launch_bounds__(256) void split_x_kernel(
    const float* __restrict__ x, __nv_bfloat16* __restrict__ xh,
    __nv_bfloat16* __restrict__ xl, int n)
{
    int i = blockIdx.x * blockDim.x + threadIdx.x;
    if (i < n) {
        float v = x[i];
        __nv_bfloat16 h = __float2bfloat16(v);
        xh[i] = h;
        xl[i] = __float2bfloat16(v - __bfloat162float(h));
    }
}

// ---------------- transpose + split weights: W[K,N] -> O[N,K] hi/lo ---------
__global__ __launch_bounds__(256) void wsplit_t_kernel(
    const float* __restrict__ W, __nv_bfloat16* __restrict__ Oh,
    __nv_bfloat16* __restrict__ Ol, int N)
{
    __shared__ float t[32][33];
    const int n0 = blockIdx.x * 32, k0 = blockIdx.y * 32;
    const int tx = threadIdx.x & 31, ty = threadIdx.x >> 5;
#pragma unroll
    for (int i = 0; i < 4; i++) {
        int k = k0 + ty + i * 8;
        int n = n0 + tx;
        t[ty + i * 8][tx] = (n < N) ? W[(size_t)k * N + n] : 0.0f;
    }
    __syncthreads();
#pragma unroll
    for (int i = 0; i < 4; i++) {
        int n = n0 + ty + i * 8;
        int k = k0 + tx;
        float v = t[tx][ty + i * 8];
        __nv_bfloat16 h = __float2bfloat16(v);
        Oh[(size_t)n * KDIM + k] = h;
        Ol[(size_t)n * KDIM + k] = __float2bfloat16(v - __bfloat162float(h));
    }
}

// ---------------- node softmax/dot/sigmoid reduction ------------------------
__global__ __launch_bounds__(256) void node_sd_kernel(
    const float* __restrict__ fi, const float* __restrict__ fs,
    const float* __restrict__ x, float* __restrict__ sd)
{
    __shared__ float xs[FF];
    __shared__ float red[32];
    const int b = blockIdx.x;
    const int tid = threadIdx.x;
    const int lane = tid & 31;
    const int warp = tid >> 5;

    xs[tid] = x[(size_t)b * FF + tid];
    xs[tid + 256] = x[(size_t)b * FF + tid + 256];
    __syncthreads();

    const float xv0 = xs[tid];
    const float xv1 = xs[tid + 256];
    const float* fib = fi + (size_t)b * (NNODES * FF);
    const float* fsb = fs + (size_t)b * (NNODES * FF);

    for (int n = 0; n < NNODES; n++) {
        const float a0 = fib[n * FF + tid];
        const float a1 = fib[n * FF + tid + 256];
        float m = fmaxf(a0, a1);
#pragma unroll
        for (int o = 16; o > 0; o >>= 1)
            m = fmaxf(m, __shfl_xor_sync(0xffffffffu, m, o));
        if (lane == 0) red[warp] = m;
        __syncthreads();
        if (warp == 0) {
            float mm = red[lane & 7];
#pragma unroll
            for (int o = 4; o > 0; o >>= 1)
                mm = fmaxf(mm, __shfl_xor_sync(0xffffffffu, mm, o));
            if (lane == 0) red[0] = mm;
        }
        __syncthreads();
        m = red[0];
        __syncthreads();

        const float e0 = __expf(a0 - m);
        const float e1 = __expf(a1 - m);
        float se = e0 + e1;
        float sx = e0 * xv0 + e1 * xv1;
        const float f0 = fsb[n * FF + tid];
        const float f1 = fsb[n * FF + tid + 256];
        float sf = e0 * f0 + e1 * f1;
#pragma unroll
        for (int o = 16; o > 0; o >>= 1) {
            se += __shfl_xor_sync(0xffffffffu, se, o);
            sx += __shfl_xor_sync(0xffffffffu, sx, o);
            sf += __shfl_xor_sync(0xffffffffu, sf, o);
        }
        if (lane == 0) { red[warp] = se; red[8 + warp] = sx; red[16 + warp] = sf; }
        __syncthreads();
        if (tid == 0) {
            float SE = 0.f, SX = 0.f, SF = 0.f;
#pragma unroll
            for (int w = 0; w < 8; w++) { SE += red[w]; SX += red[8 + w]; SF += red[16 + w]; }
            float z = (SX - SF) / SE;
            sd[b * NNODES + n] = 1.0f / (1.0f + expf(-z));
        }
        __syncthreads();
    }
}

// ---------------- tree combine ----------------------------------------------
__global__ __launch_bounds__(128) void combine_kernel(
    const float* __restrict__ sd, const float* __restrict__ lnc,
    float* __restrict__ out)
{
    __shared__ float s[NNODES];
    __shared__ float coeff[NLEAVES];
    const int b = blockIdx.x;
    const int tid = threadIdx.x;
    if (tid < NNODES) s[tid] = sd[b * NNODES + tid];
    __syncthreads();
    if (tid < NLEAVES) {
        const int l = tid;
        float p, c;
        p = s[0];            c  = ((l >> 3) & 1) ? 1.0f - p : p;
        p = s[1 + (l >> 3)]; c *= ((l >> 2) & 1) ? 1.0f - p : p;
        p = s[3 + (l >> 2)]; c *= ((l >> 1) & 1) ? 1.0f - p : p;
        p = s[7 + (l >> 1)]; c *= (l & 1)        ? 1.0f - p : p;
        coeff[l] = c;
    }
    __syncthreads();
    if (tid < CC) {
        const float* lp = lnc + (size_t)b * (NLEAVES * CC) + tid;
        float acc = 0.0f;
#pragma unroll
        for (int l = 0; l < NLEAVES; l++) acc += coeff[l] * lp[l * CC];
        out[b * CC + tid] = acc;
    }
}

// ===========================================================================
extern "C" void kernel_launch(void* const* d_in, const int* in_sizes, int n_in,
                              void* d_out, int out_size)
{
    const float* x    = (const float*)d_in[0];
    const float* w_in = (const float*)d_in[1];
    const float* b_in = (const float*)d_in[2];
    const float* g0   = (const float*)d_in[3];
    const float* be0  = (const float*)d_in[4];
    const float* bw1  = (const float*)d_in[5];
    const float* bb1  = (const float*)d_in[6];
    const float* bg1  = (const float*)d_in[7];
    const float* bbe1 = (const float*)d_in[8];
    const float* bw2  = (const float*)d_in[9];
    const float* bb2  = (const float*)d_in[10];
    const float* bg2  = (const float*)d_in[11];
    const float* bbe2 = (const float*)d_in[12];
    const float* w_fi = (const float*)d_in[13];
    const float* b_fi = (const float*)d_in[14];
    const float* w_fs = (const float*)d_in[15];
    const float* b_fs = (const float*)d_in[16];
    const float* w_lc = (const float*)d_in[17];
    const float* b_lc = (const float*)d_in[18];
    float* out = (float*)d_out;

    __nv_bfloat16 *xh, *xl, *p0h, *p0l, *p1h, *p1l, *pth, *ptl;
    __nv_bfloat16 *wih, *wil, *w1h, *w1l, *w2h, *w2l;
    __nv_bfloat16 *wfih, *wfil, *wfsh, *wfsl, *wlch, *wlcl;
    float *fi, *fs, *lc, *sdp;
    cudaGetSymbolAddress((void**)&xh, g_xh);   cudaGetSymbolAddress((void**)&xl, g_xl);
    cudaGetSymbolAddress((void**)&p0h, g_p0h); cudaGetSymbolAddress((void**)&p0l, g_p0l);
    cudaGetSymbolAddress((void**)&p1h, g_p1h); cudaGetSymbolAddress((void**)&p1l, g_p1l);
    cudaGetSymbolAddress((void**)&pth, g_pth); cudaGetSymbolAddress((void**)&ptl, g_ptl);
    cudaGetSymbolAddress((void**)&wih, g_wih); cudaGetSymbolAddress((void**)&wil, g_wil);
    cudaGetSymbolAddress((void**)&w1h, g_w1h); cudaGetSymbolAddress((void**)&w1l, g_w1l);
    cudaGetSymbolAddress((void**)&w2h, g_w2h); cudaGetSymbolAddress((void**)&w2l, g_w2l);
    cudaGetSymbolAddress((void**)&wfih, g_wfih); cudaGetSymbolAddress((void**)&wfil, g_wfil);
    cudaGetSymbolAddress((void**)&wfsh, g_wfsh); cudaGetSymbolAddress((void**)&wfsl, g_wfsl);
    cudaGetSymbolAddress((void**)&wlch, g_wlch); cudaGetSymbolAddress((void**)&wlcl, g_wlcl);
    cudaGetSymbolAddress((void**)&fi, g_fi);   cudaGetSymbolAddress((void**)&fs, g_fs);
    cudaGetSymbolAddress((void**)&lc, g_lc);   cudaGetSymbolAddress((void**)&sdp, g_sd);

    cudaFuncSetAttribute(gemm_mma<1, 0>, cudaFuncAttributeMaxDynamicSharedMemorySize, SMEM_BYTES);
    cudaFuncSetAttribute(gemm_mma<2, 0>, cudaFuncAttributeMaxDynamicSharedMemorySize, SMEM_BYTES);
    cudaFuncSetAttribute(gemm_mma<3, 0>, cudaFuncAttributeMaxDynamicSharedMemorySize, SMEM_BYTES);
    cudaFuncSetAttribute(gemm_mma<0, 1>, cudaFuncAttributeMaxDynamicSharedMemorySize, SMEM_BYTES);

    // ---- prep: split inputs / transpose+split weights ----
    split_x_kernel<<<(BQ * FF + 255) / 256, 256>>>(x, xh, xl, BQ * FF);
    wsplit_t_kernel<<<dim3(HH / 32, KDIM / 32), 256>>>(w_in, wih, wil, HH);
    wsplit_t_kernel<<<dim3(HH / 32, KDIM / 32), 256>>>(bw1, w1h, w1l, HH);
    wsplit_t_kernel<<<dim3(HH / 32, KDIM / 32), 256>>>(bw1 + HH * HH, w1h + HH * HH, w1l + HH * HH, HH);
    wsplit_t_kernel<<<dim3(HH / 32, KDIM / 32), 256>>>(bw2, w2h, w2l, HH);
    wsplit_t_kernel<<<dim3(HH / 32, KDIM / 32), 256>>>(bw2 + HH * HH, w2h + HH * HH, w2l + HH * HH, HH);
    wsplit_t_kernel<<<dim3(NFI / 32, KDIM / 32), 256>>>(w_fi, wfih, wfil, NFI);
    wsplit_t_kernel<<<dim3(NFI / 32, KDIM / 32), 256>>>(w_fs, wfsh, wfsl, NFI);
    wsplit_t_kernel<<<dim3(NLCP / 32, KDIM / 32), 256>>>(w_lc, wlch, wlcl, NLC);

    const dim3 g512(HH / 128, BQ / 128);      // (4, 64)
    const dim3 gfi(NFI / 128, BQ / 128);      // (60, 64)
    const dim3 glc(NLCP / 128, BQ / 128);     // (13, 64)

    // trunk
    gemm_mma<1, 0><<<g512, 256, SMEM_BYTES>>>(xh, xl, wih, wil,
        nullptr, p0h, p0l, HH, b_in, g0, be0, nullptr, nullptr);
    gemm_mma<2, 0><<<g512, 256, SMEM_BYTES>>>(p0h, p0l, w1h, w1l,
        nullptr, pth, ptl, HH, bb1, bg1, bbe1, nullptr, nullptr);
    gemm_mma<3, 0><<<g512, 256, SMEM_BYTES>>>(pth, ptl, w2h, w2l,
        nullptr, p1h, p1l, HH, bb2, bg2, bbe2, p0h, p0l);
    gemm_mma<2, 0><<<g512, 256, SMEM_BYTES>>>(p1h, p1l, w1h + HH * HH, w1l + HH * HH,
        nullptr, pth, ptl, HH, bb1 + HH, bg1 + HH, bbe1 + HH, nullptr, nullptr);
    gemm_mma<3, 0><<<g512, 256, SMEM_BYTES>>>(pth, ptl, w2h + HH * HH, w2l + HH * HH,
        nullptr, p0h, p0l, HH, bb2 + HH, bg2 + HH, bbe2 + HH, p1h, p1l);
    // heads (h lives in p0)
    gemm_mma<0, 1><<<gfi, 256, SMEM_BYTES>>>(p0h, p0l, wfih, wfil,
        fi, nullptr, nullptr, NFI, b_fi, nullptr, nullptr, nullptr, nullptr);
    gemm_mma<0, 1><<<gfi, 256, SMEM_BYTES>>>(p0h, p0l, wfsh, wfsl,
        fs, nullptr, nullptr, NFI, b_fs, nullptr, nullptr, nullptr, nullptr);
    gemm_mma<0, 1><<<glc, 256, SMEM_BYTES>>>(p0h, p0l, wlch, wlcl,
        lc, nullptr, nullptr, NLC, b_lc, nullptr, nullptr, nullptr, nullptr);
    // reductions
    node_sd_kernel<<<BQ, 256>>>(fi, fs, x, sdp);
    combine_kernel<<<BQ, 128>>>(sdp, lc, out);
}

// round 4
// speedup vs baseline: 2.2101x; 1.0334x over previous
#include <cuda_runtime.h>
#include <cuda_bf16.h>
#include <cstdint>
#include <math.h>

// ===========================================================================
// DTHyperNet via sm_80-compatible tensor cores (mma.sync bf16, fp32 accum)
// GEMMs: D = Ah*Bh + Ah*Bl + Al*Bh  (2-way bf16 split, virtual K = 1536)
// Head fi/fs GEMMs fused with the softmax/dot reduction (no fi/fs in DRAM).
// ===========================================================================

#define BQ 8192
#define FF 512
#define HH 512
#define CC 100
#define NNODES 15
#define NLEAVES 16
#define NFI 7680
#define NLC 1600
#define NLCP 1664
#define KDIM 512
#define EPSV 1e-5f

// -------------------- device scratch (no allocations allowed) --------------
__device__ __nv_bfloat16 g_xh[BQ * FF], g_xl[BQ * FF];
__device__ __nv_bfloat16 g_p0h[BQ * HH], g_p0l[BQ * HH];
__device__ __nv_bfloat16 g_p1h[BQ * HH], g_p1l[BQ * HH];
__device__ __nv_bfloat16 g_pth[BQ * HH], g_ptl[BQ * HH];
__device__ __nv_bfloat16 g_wih[HH * HH], g_wil[HH * HH];
__device__ __nv_bfloat16 g_w1h[2 * HH * HH], g_w1l[2 * HH * HH];
__device__ __nv_bfloat16 g_w2h[2 * HH * HH], g_w2l[2 * HH * HH];
__device__ __nv_bfloat16 g_wfih[NFI * HH], g_wfil[NFI * HH];
__device__ __nv_bfloat16 g_wfsh[NFI * HH], g_wfsl[NFI * HH];
__device__ __nv_bfloat16 g_wlch[NLCP * HH], g_wlcl[NLCP * HH];
__device__ float g_lc[(size_t)BQ * NLC];
// per-slice partials of the node reduction: [B, 15, 16]
__device__ float g_pse[(size_t)BQ * NNODES * 16];
__device__ float g_psx[(size_t)BQ * NNODES * 16];
__device__ float g_psf[(size_t)BQ * NNODES * 16];

// -------------------- PTX helpers (sm_80 baseline only) --------------------
__device__ __forceinline__ uint32_t smem_u32(const void* p) {
    uint32_t a;
    asm("{ .reg .u64 t; cvta.to.shared.u64 t, %1; cvt.u32.u64 %0, t; }"
        : "=r"(a) : "l"(p));
    return a;
}
#define CP16(dst, src) \
    asm volatile("cp.async.cg.shared.global [%0], [%1], 16;" :: "r"(dst), "l"(src))
#define CP_COMMIT() asm volatile("cp.async.commit_group;" ::: "memory")
#define CP_WAIT0() asm volatile("cp.async.wait_group 0;" ::: "memory")
#define CP_WAIT1() asm volatile("cp.async.wait_group 1;" ::: "memory")

__device__ __forceinline__ void ldsm4(uint32_t* r, uint32_t addr) {
    asm volatile("ldmatrix.sync.aligned.m8n8.x4.shared.b16 {%0,%1,%2,%3}, [%4];"
                 : "=r"(r[0]), "=r"(r[1]), "=r"(r[2]), "=r"(r[3]) : "r"(addr));
}
__device__ __forceinline__ void mma16816(float* c, const uint32_t* a,
                                         uint32_t b0, uint32_t b1) {
    asm volatile(
        "mma.sync.aligned.m16n8k16.row.col.f32.bf16.bf16.f32 "
        "{%0,%1,%2,%3}, {%4,%5,%6,%7}, {%8,%9}, {%0,%1,%2,%3};"
        : "+f"(c[0]), "+f"(c[1]), "+f"(c[2]), "+f"(c[3])
        : "r"(a[0]), "r"(a[1]), "r"(a[2]), "r"(a[3]), "r"(b0), "r"(b1));
}

// smem tile: 128 rows x 32 bf16, padded row stride 80 bytes (conflict-free)
#define ROWB 80
#define TILEB (128 * ROWB)          // 10240
#define NSTAGE 3
#define KSTAGES 48                  // 1536 / 32
#define SMEM_G (NSTAGE * 2 * TILEB) // 61440  (A + B)
#define SMEM_F (NSTAGE * 3 * TILEB) // 92160  (A + Bfi + Bfs)

// ===========================================================================
// Generic GEMM (trunk + lc):  grid (N/128, BQ/128), 256 thr, 8 warps 64x32
// EPI 0: +bias -> fp32    1: bn+relu -> split    2: bn+gelu -> split
// EPI 3: bn+gelu+residual -> split
// ===========================================================================
template <int EPI, int F32OUT>
__global__ __launch_bounds__(256) void gemm_mma(
    const __nv_bfloat16* __restrict__ Ah, const __nv_bfloat16* __restrict__ Al,
    const __nv_bfloat16* __restrict__ Bh, const __nv_bfloat16* __restrict__ Bl,
    float* __restrict__ Cf, __nv_bfloat16* __restrict__ Ch, __nv_bfloat16* __restrict__ Cl,
    int Nout,
    const float* __restrict__ bias, const float* __restrict__ gamma,
    const float* __restrict__ beta,
    const __nv_bfloat16* __restrict__ Rh, const __nv_bfloat16* __restrict__ Rl)
{
    extern __shared__ char dsm[];
    const uint32_t sb = smem_u32(dsm);

    const int tid = threadIdx.x;
    const int lane = tid & 31;
    const int wid = tid >> 5;
    const int warp_m = wid >> 2;
    const int warp_n = wid & 3;
    const int bm = blockIdx.y * 128;
    const int bn = blockIdx.x * 128;

    const char* Aparts[3] = { (const char*)Ah + (size_t)bm * 1024,
                              (const char*)Ah + (size_t)bm * 1024,
                              (const char*)Al + (size_t)bm * 1024 };
    const char* Bparts[3] = { (const char*)Bh + (size_t)bn * 1024,
                              (const char*)Bl + (size_t)bn * 1024,
                              (const char*)Bh + (size_t)bn * 1024 };

    const int lr0 = tid >> 2;
    const int lc0 = (tid & 3) * 16;
    const int arow = (lane & 7) + ((lane >> 3) & 1) * 8;
    const int asel = lane >> 4;
    const int brow = ((lane >> 4) & 1) * 8 + (lane & 7);
    const int bsel = (lane >> 3) & 1;
    const uint32_t a_lane = (uint32_t)(warp_m * 64 + arow) * ROWB;
    const uint32_t b_lane = (uint32_t)(warp_n * 32 + brow) * ROWB;

    float acc[4][4][4];
#pragma unroll
    for (int i = 0; i < 4; i++)
#pragma unroll
        for (int j = 0; j < 4; j++)
#pragma unroll
            for (int u = 0; u < 4; u++) acc[i][j][u] = 0.0f;

    auto load_stage = [&](int s, int buf) {
        const int p = s >> 4;
        const int ko = (s & 15) * 64;
        const uint32_t ab = sb + buf * (2 * TILEB);
        const uint32_t bb = ab + TILEB;
        const char* As = Aparts[p] + ko;
        const char* Bs = Bparts[p] + ko;
#pragma unroll
        for (int i = 0; i < 2; i++) {
            const int r = lr0 + i * 64;
            CP16(ab + r * ROWB + lc0, As + (size_t)r * 1024 + lc0);
            CP16(bb + r * ROWB + lc0, Bs + (size_t)r * 1024 + lc0);
        }
    };

    load_stage(0, 0); CP_COMMIT();
    load_stage(1, 1); CP_COMMIT();

    int buf = 0;
    for (int s = 0; s < KSTAGES; s++) {
        if (s + 2 < KSTAGES) { CP_WAIT1(); } else { CP_WAIT0(); }
        __syncthreads();
        if (s + 2 < KSTAGES) {
            int nb = buf + 2; if (nb >= NSTAGE) nb -= NSTAGE;
            load_stage(s + 2, nb);
            CP_COMMIT();
        }
        const uint32_t ab = sb + buf * (2 * TILEB);
        const uint32_t bb = ab + TILEB;
#pragma unroll
        for (int kh = 0; kh < 2; kh++) {
            uint32_t af[4][4], bf[2][4];
            const uint32_t kadd = kh * 32;
#pragma unroll
            for (int m = 0; m < 4; m++)
                ldsm4(af[m], ab + a_lane + m * (16 * ROWB) + kadd + asel * 16);
#pragma unroll
            for (int n2 = 0; n2 < 2; n2++)
                ldsm4(bf[n2], bb + b_lane + n2 * (16 * ROWB) + kadd + bsel * 16);
#pragma unroll
            for (int m = 0; m < 4; m++)
#pragma unroll
                for (int n = 0; n < 4; n++)
                    mma16816(acc[m][n], af[m],
                             bf[n >> 1][(n & 1) * 2 + 0], bf[n >> 1][(n & 1) * 2 + 1]);
        }
        buf++; if (buf == NSTAGE) buf = 0;
    }

    const float RS = rsqrtf(1.0f + EPSV);
    const int lm = lane >> 2;
    const int ln2 = (lane & 3) * 2;
    const int row0 = bm + warp_m * 64;
    const int col0 = bn + warp_n * 32;

#pragma unroll
    for (int m = 0; m < 4; m++) {
#pragma unroll
        for (int n = 0; n < 4; n++) {
            const int gn = col0 + n * 8 + ln2;
            const int r_lo = row0 + m * 16 + lm;
            const int r_hi = r_lo + 8;
            float* c = acc[m][n];
            if (F32OUT) {
                if (gn < Nout) {
                    const float bz0 = bias[gn], bz1 = bias[gn + 1];
                    *(float2*)(Cf + (size_t)r_lo * Nout + gn) = make_float2(c[0] + bz0, c[1] + bz1);
                    *(float2*)(Cf + (size_t)r_hi * Nout + gn) = make_float2(c[2] + bz0, c[3] + bz1);
                }
            } else {
                const float bz0 = bias[gn], bz1 = bias[gn + 1];
                const float s0 = gamma[gn] * RS, s1 = gamma[gn + 1] * RS;
                const float e0 = beta[gn], e1 = beta[gn + 1];
                float v[4];
                v[0] = (c[0] + bz0) * s0 + e0; v[1] = (c[1] + bz1) * s1 + e1;
                v[2] = (c[2] + bz0) * s0 + e0; v[3] = (c[3] + bz1) * s1 + e1;
#pragma unroll
                for (int u = 0; u < 4; u++) {
                    if (EPI == 1) v[u] = fmaxf(v[u], 0.0f);
                    else v[u] = 0.5f * v[u] * (1.0f + erff(v[u] * 0.70710678118654752f));
                }
                if (EPI == 3) {
                    const size_t o0 = (size_t)r_lo * HH + gn;
                    const size_t o1 = (size_t)r_hi * HH + gn;
                    __nv_bfloat162 rh0 = *(const __nv_bfloat162*)(Rh + o0);
                    __nv_bfloat162 rl0 = *(const __nv_bfloat162*)(Rl + o0);
                    __nv_bfloat162 rh1 = *(const __nv_bfloat162*)(Rh + o1);
                    __nv_bfloat162 rl1 = *(const __nv_bfloat162*)(Rl + o1);
                    v[0] += __bfloat162float(rh0.x) + __bfloat162float(rl0.x);
                    v[1] += __bfloat162float(rh0.y) + __bfloat162float(rl0.y);
                    v[2] += __bfloat162float(rh1.x) + __bfloat162float(rl1.x);
                    v[3] += __bfloat162float(rh1.y) + __bfloat162float(rl1.y);
                }
                __nv_bfloat162 hp0, lp0, hp1, lp1;
                hp0.x = __float2bfloat16(v[0]); hp0.y = __float2bfloat16(v[1]);
                lp0.x = __float2bfloat16(v[0] - __bfloat162float(hp0.x));
                lp0.y = __float2bfloat16(v[1] - __bfloat162float(hp0.y));
                hp1.x = __float2bfloat16(v[2]); hp1.y = __float2bfloat16(v[3]);
                lp1.x = __float2bfloat16(v[2] - __bfloat162float(hp1.x));
                lp1.y = __float2bfloat16(v[3] - __bfloat162float(hp1.y));
                *(__nv_bfloat162*)(Ch + (size_t)r_lo * HH + gn) = hp0;
                *(__nv_bfloat162*)(Cl + (size_t)r_lo * HH + gn) = lp0;
                *(__nv_bfloat162*)(Ch + (size_t)r_hi * HH + gn) = hp1;
                *(__nv_bfloat162*)(Cl + (size_t)r_hi * HH + gn) = lp1;
            }
        }
    }
}

// ===========================================================================
// Fused fi/fs head + node reduction.
// grid (60, 64). Computes fi and fs 128x128 tiles in registers, then per-warp
// 32-col slice partials of  se = sum exp(fi), sx = sum exp(fi)*x,
// sf = sum exp(fi)*fs  -> g_ps*[row*15+node)*16 + slice].
// ===========================================================================
__global__ __launch_bounds__(256, 1) void gemm_fifs(
    const __nv_bfloat16* __restrict__ Ah, const __nv_bfloat16* __restrict__ Al,
    const __nv_bfloat16* __restrict__ BiH, const __nv_bfloat16* __restrict__ BiL,
    const __nv_bfloat16* __restrict__ BsH, const __nv_bfloat16* __restrict__ BsL,
    const float* __restrict__ x,
    const float* __restrict__ b_fi, const float* __restrict__ b_fs,
    float* __restrict__ pse, float* __restrict__ psx, float* __restrict__ psf)
{
    extern __shared__ char dsm[];
    const uint32_t sb = smem_u32(dsm);

    const int tid = threadIdx.x;
    const int lane = tid & 31;
    const int wid = tid >> 5;
    const int warp_m = wid >> 2;
    const int warp_n = wid & 3;
    const int ct = blockIdx.x;         // col tile 0..59
    const int bm = blockIdx.y * 128;
    const int bn = ct * 128;
    const int node = ct >> 2;
    const int slice = (ct & 3) * 4 + warp_n;
    const int xbase = (ct & 3) * 128 + warp_n * 32;   // col in x within node

    const char* Aparts[3] = { (const char*)Ah + (size_t)bm * 1024,
                              (const char*)Ah + (size_t)bm * 1024,
                              (const char*)Al + (size_t)bm * 1024 };
    const char* BiP[3] = { (const char*)BiH + (size_t)bn * 1024,
                           (const char*)BiL + (size_t)bn * 1024,
                           (const char*)BiH + (size_t)bn * 1024 };
    const char* BsP[3] = { (const char*)BsH + (size_t)bn * 1024,
                           (const char*)BsL + (size_t)bn * 1024,
                           (const char*)BsH + (size_t)bn * 1024 };

    const int lr0 = tid >> 2;
    const int lc0 = (tid & 3) * 16;
    const int arow = (lane & 7) + ((lane >> 3) & 1) * 8;
    const int asel = lane >> 4;
    const int brow = ((lane >> 4) & 1) * 8 + (lane & 7);
    const int bsel = (lane >> 3) & 1;
    const uint32_t a_lane = (uint32_t)(warp_m * 64 + arow) * ROWB;
    const uint32_t b_lane = (uint32_t)(warp_n * 32 + brow) * ROWB;

    float accI[4][4][4], accS[4][4][4];
#pragma unroll
    for (int i = 0; i < 4; i++)
#pragma unroll
        for (int j = 0; j < 4; j++)
#pragma unroll
            for (int u = 0; u < 4; u++) { accI[i][j][u] = 0.0f; accS[i][j][u] = 0.0f; }

    auto load_stage = [&](int s, int buf) {
        const int p = s >> 4;
        const int ko = (s & 15) * 64;
        const uint32_t ab = sb + buf * (3 * TILEB);
        const uint32_t ib = ab + TILEB;
        const uint32_t qb = ib + TILEB;
        const char* As = Aparts[p] + ko;
        const char* Is = BiP[p] + ko;
        const char* Qs = BsP[p] + ko;
#pragma unroll
        for (int i = 0; i < 2; i++) {
            const int r = lr0 + i * 64;
            CP16(ab + r * ROWB + lc0, As + (size_t)r * 1024 + lc0);
            CP16(ib + r * ROWB + lc0, Is + (size_t)r * 1024 + lc0);
            CP16(qb + r * ROWB + lc0, Qs + (size_t)r * 1024 + lc0);
        }
    };

    load_stage(0, 0); CP_COMMIT();
    load_stage(1, 1); CP_COMMIT();

    int buf = 0;
    for (int s = 0; s < KSTAGES; s++) {
        if (s + 2 < KSTAGES) { CP_WAIT1(); } else { CP_WAIT0(); }
        __syncthreads();
        if (s + 2 < KSTAGES) {
            int nb = buf + 2; if (nb >= NSTAGE) nb -= NSTAGE;
            load_stage(s + 2, nb);
            CP_COMMIT();
        }
        const uint32_t ab = sb + buf * (3 * TILEB);
        const uint32_t ib = ab + TILEB;
        const uint32_t qb = ib + TILEB;
#pragma unroll
        for (int kh = 0; kh < 2; kh++) {
            uint32_t af[4][4], bi[2][4], bq[2][4];
            const uint32_t kadd = kh * 32;
#pragma unroll
            for (int m = 0; m < 4; m++)
                ldsm4(af[m], ab + a_lane + m * (16 * ROWB) + kadd + asel * 16);
#pragma unroll
            for (int n2 = 0; n2 < 2; n2++) {
                ldsm4(bi[n2], ib + b_lane + n2 * (16 * ROWB) + kadd + bsel * 16);
                ldsm4(bq[n2], qb + b_lane + n2 * (16 * ROWB) + kadd + bsel * 16);
            }
#pragma unroll
            for (int m = 0; m < 4; m++)
#pragma unroll
                for (int n = 0; n < 4; n++) {
                    mma16816(accI[m][n], af[m],
                             bi[n >> 1][(n & 1) * 2 + 0], bi[n >> 1][(n & 1) * 2 + 1]);
                    mma16816(accS[m][n], af[m],
                             bq[n >> 1][(n & 1) * 2 + 0], bq[n >> 1][(n & 1) * 2 + 1]);
                }
        }
        buf++; if (buf == NSTAGE) buf = 0;
    }

    // -------- fused reduction epilogue --------
    const int lm = lane >> 2;
    const int ln2 = (lane & 3) * 2;
    const int row0 = bm + warp_m * 64;
    const int col0 = bn + warp_n * 32;

    float se[8], sx[8], sf[8];
#pragma unroll
    for (int i = 0; i < 8; i++) { se[i] = 0.f; sx[i] = 0.f; sf[i] = 0.f; }

#pragma unroll
    for (int n = 0; n < 4; n++) {
        const int gn = col0 + n * 8 + ln2;
        const int xc = xbase + n * 8 + ln2;
        const float bi0 = b_fi[gn], bi1 = b_fi[gn + 1];
        const float bs0 = b_fs[gn], bs1 = b_fs[gn + 1];
#pragma unroll
        for (int m = 0; m < 4; m++) {
            const int r_lo = row0 + m * 16 + lm;
            const int r_hi = r_lo + 8;
            const float* ci = accI[m][n];
            const float* cs = accS[m][n];
            const float e0 = __expf(ci[0] + bi0);
            const float e1 = __expf(ci[1] + bi1);
            const float e2 = __expf(ci[2] + bi0);
            const float e3 = __expf(ci[3] + bi1);
            const float2 x0 = *(const float2*)(x + (size_t)r_lo * FF + xc);
            const float2 x1 = *(const float2*)(x + (size_t)r_hi * FF + xc);
            se[m * 2 + 0] += e0 + e1;
            se[m * 2 + 1] += e2 + e3;
            sx[m * 2 + 0] += e0 * x0.x + e1 * x0.y;
            sx[m * 2 + 1] += e2 * x1.x + e3 * x1.y;
            sf[m * 2 + 0] += e0 * (cs[0] + bs0) + e1 * (cs[1] + bs1);
            sf[m * 2 + 1] += e2 * (cs[2] + bs0) + e3 * (cs[3] + bs1);
        }
    }

    // reduce across the 4 lanes sharing a row (lane&3)
#pragma unroll
    for (int i = 0; i < 8; i++) {
        se[i] += __shfl_xor_sync(0xffffffffu, se[i], 1);
        se[i] += __shfl_xor_sync(0xffffffffu, se[i], 2);
        sx[i] += __shfl_xor_sync(0xffffffffu, sx[i], 1);
        sx[i] += __shfl_xor_sync(0xffffffffu, sx[i], 2);
        sf[i] += __shfl_xor_sync(0xffffffffu, sf[i], 1);
        sf[i] += __shfl_xor_sync(0xffffffffu, sf[i], 2);
    }
    if ((lane & 3) == 0) {
#pragma unroll
        for (int i = 0; i < 8; i++) {
            const int row = row0 + (i >> 1) * 16 + lm + (i & 1) * 8;
            const size_t o = ((size_t)row * NNODES + node) * 16 + slice;
            pse[o] = se[i]; psx[o] = sx[i]; psf[o] = sf[i];
        }
    }
}

// ---------------- split x into bf16 hi/lo -----------------------------------
__global__ __launch_bounds__(256) void split_x_kernel(
    const float* __restrict__ x, __nv_bfloat16* __restrict__ xh,
    __nv_bfloat16* __restrict__ xl, int n)
{
    int i = blockIdx.x * blockDim.x + threadIdx.x;
    if (i < n) {
        float v = x[i];
        __nv_bfloat16 h = __float2bfloat16(v);
        xh[i] = h;
        xl[i] = __float2bfloat16(v - __bfloat162float(h));
    }
}

// ---------------- transpose + split weights: W[K,N] -> O[N,K] hi/lo ---------
__global__ __launch_bounds__(256) void wsplit_t_kernel(
    const float* __restrict__ W, __nv_bfloat16* __restrict__ Oh,
    __nv_bfloat16* __restrict__ Ol, int N)
{
    __shared__ float t[32][33];
    const int n0 = blockIdx.x * 32, k0 = blockIdx.y * 32;
    const int tx = threadIdx.x & 31, ty = threadIdx.x >> 5;
#pragma unroll
    for (int i = 0; i < 4; i++) {
        int k = k0 + ty + i * 8;
        int n = n0 + tx;
        t[ty + i * 8][tx] = (n < N) ? W[(size_t)k * N + n] : 0.0f;
    }
    __syncthreads();
#pragma unroll
    for (int i = 0; i < 4; i++) {
        int n = n0 + ty + i * 8;
        int k = k0 + tx;
        float v = t[tx][ty + i * 8];
        __nv_bfloat16 h = __float2bfloat16(v);
        Oh[(size_t)n * KDIM + k] = h;
        Ol[(size_t)n * KDIM + k] = __float2bfloat16(v - __bfloat162float(h));
    }
}

// ---------------- sd + tree combine -----------------------------------------
__global__ __launch_bounds__(128) void sd_combine_kernel(
    const float* __restrict__ pse, const float* __restrict__ psx,
    const float* __restrict__ psf, const float* __restrict__ lnc,
    float* __restrict__ out)
{
    __shared__ float s_sd[NNODES];
    __shared__ float coeff[NLEAVES];
    const int b = blockIdx.x;
    const int tid = threadIdx.x;

    if (tid < NNODES) {
        const size_t base = ((size_t)b * NNODES + tid) * 16;
        float se = 0.f, sx = 0.f, sf = 0.f;
#pragma unroll
        for (int s = 0; s < 16; s++) {
            se += pse[base + s]; sx += psx[base + s]; sf += psf[base + s];
        }
        const float z = (sx - sf) / se;
        s_sd[tid] = 1.0f / (1.0f + expf(-z));
    }
    __syncthreads();
    if (tid < NLEAVES) {
        const int l = tid;
        float p, c;
        p = s_sd[0];            c  = ((l >> 3) & 1) ? 1.0f - p : p;
        p = s_sd[1 + (l >> 3)]; c *= ((l >> 2) & 1) ? 1.0f - p : p;
        p = s_sd[3 + (l >> 2)]; c *= ((l >> 1) & 1) ? 1.0f - p : p;
        p = s_sd[7 + (l >> 1)]; c *= (l & 1)        ? 1.0f - p : p;
        coeff[l] = c;
    }
    __syncthreads();
    if (tid < CC) {
        const float* lp = lnc + (size_t)b * (NLEAVES * CC) + tid;
        float acc = 0.0f;
#pragma unroll
        for (int l = 0; l < NLEAVES; l++) acc += coeff[l] * lp[l * CC];
        out[b * CC + tid] = acc;
    }
}

// ===========================================================================
extern "C" void kernel_launch(void* const* d_in, const int* in_sizes, int n_in,
                              void* d_out, int out_size)
{
    const float* x    = (const float*)d_in[0];
    const float* w_in = (const float*)d_in[1];
    const float* b_in = (const float*)d_in[2];
    const float* g0   = (const float*)d_in[3];
    const float* be0  = (const float*)d_in[4];
    const float* bw1  = (const float*)d_in[5];
    const float* bb1  = (const float*)d_in[6];
    const float* bg1  = (const float*)d_in[7];
    const float* bbe1 = (const float*)d_in[8];
    const float* bw2  = (const float*)d_in[9];
    const float* bb2  = (const float*)d_in[10];
    const float* bg2  = (const float*)d_in[11];
    const float* bbe2 = (const float*)d_in[12];
    const float* w_fi = (const float*)d_in[13];
    const float* b_fi = (const float*)d_in[14];
    const float* w_fs = (const float*)d_in[15];
    const float* b_fs = (const float*)d_in[16];
    const float* w_lc = (const float*)d_in[17];
    const float* b_lc = (const float*)d_in[18];
    float* out = (float*)d_out;

    __nv_bfloat16 *xh, *xl, *p0h, *p0l, *p1h, *p1l, *pth, *ptl;
    __nv_bfloat16 *wih, *wil, *w1h, *w1l, *w2h, *w2l;
    __nv_bfloat16 *wfih, *wfil, *wfsh, *wfsl, *wlch, *wlcl;
    float *lc, *pse, *psx, *psf;
    cudaGetSymbolAddress((void**)&xh, g_xh);   cudaGetSymbolAddress((void**)&xl, g_xl);
    cudaGetSymbolAddress((void**)&p0h, g_p0h); cudaGetSymbolAddress((void**)&p0l, g_p0l);
    cudaGetSymbolAddress((void**)&p1h, g_p1h); cudaGetSymbolAddress((void**)&p1l, g_p1l);
    cudaGetSymbolAddress((void**)&pth, g_pth); cudaGetSymbolAddress((void**)&ptl, g_ptl);
    cudaGetSymbolAddress((void**)&wih, g_wih); cudaGetSymbolAddress((void**)&wil, g_wil);
    cudaGetSymbolAddress((void**)&w1h, g_w1h); cudaGetSymbolAddress((void**)&w1l, g_w1l);
    cudaGetSymbolAddress((void**)&w2h, g_w2h); cudaGetSymbolAddress((void**)&w2l, g_w2l);
    cudaGetSymbolAddress((void**)&wfih, g_wfih); cudaGetSymbolAddress((void**)&wfil, g_wfil);
    cudaGetSymbolAddress((void**)&wfsh, g_wfsh); cudaGetSymbolAddress((void**)&wfsl, g_wfsl);
    cudaGetSymbolAddress((void**)&wlch, g_wlch); cudaGetSymbolAddress((void**)&wlcl, g_wlcl);
    cudaGetSymbolAddress((void**)&lc, g_lc);
    cudaGetSymbolAddress((void**)&pse, g_pse);
    cudaGetSymbolAddress((void**)&psx, g_psx);
    cudaGetSymbolAddress((void**)&psf, g_psf);

    cudaFuncSetAttribute(gemm_mma<1, 0>, cudaFuncAttributeMaxDynamicSharedMemorySize, SMEM_G);
    cudaFuncSetAttribute(gemm_mma<2, 0>, cudaFuncAttributeMaxDynamicSharedMemorySize, SMEM_G);
    cudaFuncSetAttribute(gemm_mma<3, 0>, cudaFuncAttributeMaxDynamicSharedMemorySize, SMEM_G);
    cudaFuncSetAttribute(gemm_mma<0, 1>, cudaFuncAttributeMaxDynamicSharedMemorySize, SMEM_G);
    cudaFuncSetAttribute(gemm_fifs, cudaFuncAttributeMaxDynamicSharedMemorySize, SMEM_F);

    // ---- prep ----
    split_x_kernel<<<(BQ * FF + 255) / 256, 256>>>(x, xh, xl, BQ * FF);
    wsplit_t_kernel<<<dim3(HH / 32, KDIM / 32), 256>>>(w_in, wih, wil, HH);
    wsplit_t_kernel<<<dim3(HH / 32, KDIM / 32), 256>>>(bw1, w1h, w1l, HH);
    wsplit_t_kernel<<<dim3(HH / 32, KDIM / 32), 256>>>(bw1 + HH * HH, w1h + HH * HH, w1l + HH * HH, HH);
    wsplit_t_kernel<<<dim3(HH / 32, KDIM / 32), 256>>>(bw2, w2h, w2l, HH);
    wsplit_t_kernel<<<dim3(HH / 32, KDIM / 32), 256>>>(bw2 + HH * HH, w2h + HH * HH, w2l + HH * HH, HH);
    wsplit_t_kernel<<<dim3(NFI / 32, KDIM / 32), 256>>>(w_fi, wfih, wfil, NFI);
    wsplit_t_kernel<<<dim3(NFI / 32, KDIM / 32), 256>>>(w_fs, wfsh, wfsl, NFI);
    wsplit_t_kernel<<<dim3(NLCP / 32, KDIM / 32), 256>>>(w_lc, wlch, wlcl, NLC);

    const dim3 g512(HH / 128, BQ / 128);
    const dim3 gfi(NFI / 128, BQ / 128);
    const dim3 glc(NLCP / 128, BQ / 128);

    // trunk
    gemm_mma<1, 0><<<g512, 256, SMEM_G>>>(xh, xl, wih, wil,
        nullptr, p0h, p0l, HH, b_in, g0, be0, nullptr, nullptr);
    gemm_mma<2, 0><<<g512, 256, SMEM_G>>>(p0h, p0l, w1h, w1l,
        nullptr, pth, ptl, HH, bb1, bg1, bbe1, nullptr, nullptr);
    gemm_mma<3, 0><<<g512, 256, SMEM_G>>>(pth, ptl, w2h, w2l,
        nullptr, p1h, p1l, HH, bb2, bg2, bbe2, p0h, p0l);
    gemm_mma<2, 0><<<g512, 256, SMEM_G>>>(p1h, p1l, w1h + HH * HH, w1l + HH * HH,
        nullptr, pth, ptl, HH, bb1 + HH, bg1 + HH, bbe1 + HH, nullptr, nullptr);
    gemm_mma<3, 0><<<g512, 256, SMEM_G>>>(pth, ptl, w2h + HH * HH, w2l + HH * HH,
        nullptr, p0h, p0l, HH, bb2 + HH, bg2 + HH, bbe2 + HH, p1h, p1l);
    // fused heads + node reduction (h lives in p0)
    gemm_fifs<<<gfi, 256, SMEM_F>>>(p0h, p0l, wfih, wfil, wfsh, wfsl,
                                    x, b_fi, b_fs, pse, psx, psf);
    gemm_mma<0, 1><<<glc, 256, SMEM_G>>>(p0h, p0l, wlch, wlcl,
        lc, nullptr, nullptr, NLC, b_lc, nullptr, nullptr, nullptr, nullptr);
    // final reduction
    sd_combine_kernel<<<BQ, 128>>>(pse, psx, psf, lc, out);
}

// round 5
// speedup vs baseline: 2.2725x; 1.0282x over previous
#include <cuda_runtime.h>
#include <cuda_bf16.h>
#include <cstdint>
#include <math.h>

// ===========================================================================
// DTHyperNet via sm_80-compatible tensor cores (mma.sync bf16, fp32 accum)
// GEMMs: D = Ah*Bh + Ah*Bl + Al*Bh  (2-way bf16 split, virtual K = 1536)
// fi/fs head GEMMs fused with node reduction; fused kernel uses 512 threads
// (16 warps, 32x32 warp tiles) to keep 16 warps/SM at 1 CTA/SM.
// ===========================================================================

#define BQ 8192
#define FF 512
#define HH 512
#define CC 100
#define NNODES 15
#define NLEAVES 16
#define NFI 7680
#define NLC 1600
#define NLCP 1664
#define KDIM 512
#define EPSV 1e-5f

// -------------------- device scratch (no allocations allowed) --------------
__device__ __nv_bfloat16 g_xh[BQ * FF], g_xl[BQ * FF];
__device__ __nv_bfloat16 g_p0h[BQ * HH], g_p0l[BQ * HH];
__device__ __nv_bfloat16 g_p1h[BQ * HH], g_p1l[BQ * HH];
__device__ __nv_bfloat16 g_pth[BQ * HH], g_ptl[BQ * HH];
__device__ __nv_bfloat16 g_wih[HH * HH], g_wil[HH * HH];
__device__ __nv_bfloat16 g_w1h[2 * HH * HH], g_w1l[2 * HH * HH];
__device__ __nv_bfloat16 g_w2h[2 * HH * HH], g_w2l[2 * HH * HH];
__device__ __nv_bfloat16 g_wfih[NFI * HH], g_wfil[NFI * HH];
__device__ __nv_bfloat16 g_wfsh[NFI * HH], g_wfsl[NFI * HH];
__device__ __nv_bfloat16 g_wlch[NLCP * HH], g_wlcl[NLCP * HH];
__device__ float g_lc[(size_t)BQ * NLC];
__device__ float g_pse[(size_t)BQ * NNODES * 16];
__device__ float g_psx[(size_t)BQ * NNODES * 16];
__device__ float g_psf[(size_t)BQ * NNODES * 16];

// -------------------- PTX helpers (sm_80 baseline only) --------------------
__device__ __forceinline__ uint32_t smem_u32(const void* p) {
    uint32_t a;
    asm("{ .reg .u64 t; cvta.to.shared.u64 t, %1; cvt.u32.u64 %0, t; }"
        : "=r"(a) : "l"(p));
    return a;
}
#define CP16(dst, src) \
    asm volatile("cp.async.cg.shared.global [%0], [%1], 16;" :: "r"(dst), "l"(src))
#define CP_COMMIT() asm volatile("cp.async.commit_group;" ::: "memory")
#define CP_WAIT0() asm volatile("cp.async.wait_group 0;" ::: "memory")
#define CP_WAIT1() asm volatile("cp.async.wait_group 1;" ::: "memory")

__device__ __forceinline__ void ldsm4(uint32_t* r, uint32_t addr) {
    asm volatile("ldmatrix.sync.aligned.m8n8.x4.shared.b16 {%0,%1,%2,%3}, [%4];"
                 : "=r"(r[0]), "=r"(r[1]), "=r"(r[2]), "=r"(r[3]) : "r"(addr));
}
__device__ __forceinline__ void mma16816(float* c, const uint32_t* a,
                                         uint32_t b0, uint32_t b1) {
    asm volatile(
        "mma.sync.aligned.m16n8k16.row.col.f32.bf16.bf16.f32 "
        "{%0,%1,%2,%3}, {%4,%5,%6,%7}, {%8,%9}, {%0,%1,%2,%3};"
        : "+f"(c[0]), "+f"(c[1]), "+f"(c[2]), "+f"(c[3])
        : "r"(a[0]), "r"(a[1]), "r"(a[2]), "r"(a[3]), "r"(b0), "r"(b1));
}

#define ROWB 80
#define TILEB (128 * ROWB)          // 10240
#define NSTAGE 3
#define KSTAGES 48                  // 1536 / 32
#define SMEM_G (NSTAGE * 2 * TILEB) // 61440
#define SMEM_F (NSTAGE * 3 * TILEB) // 92160

// ===========================================================================
// Generic GEMM (trunk + lc): 256 thr, 8 warps (2x4), 64x32 warp tiles
// ===========================================================================
template <int EPI, int F32OUT>
__global__ __launch_bounds__(256) void gemm_mma(
    const __nv_bfloat16* __restrict__ Ah, const __nv_bfloat16* __restrict__ Al,
    const __nv_bfloat16* __restrict__ Bh, const __nv_bfloat16* __restrict__ Bl,
    float* __restrict__ Cf, __nv_bfloat16* __restrict__ Ch, __nv_bfloat16* __restrict__ Cl,
    int Nout,
    const float* __restrict__ bias, const float* __restrict__ gamma,
    const float* __restrict__ beta,
    const __nv_bfloat16* __restrict__ Rh, const __nv_bfloat16* __restrict__ Rl)
{
    extern __shared__ char dsm[];
    const uint32_t sb = smem_u32(dsm);

    const int tid = threadIdx.x;
    const int lane = tid & 31;
    const int wid = tid >> 5;
    const int warp_m = wid >> 2;
    const int warp_n = wid & 3;
    const int bm = blockIdx.y * 128;
    const int bn = blockIdx.x * 128;

    const char* Aparts[3] = { (const char*)Ah + (size_t)bm * 1024,
                              (const char*)Ah + (size_t)bm * 1024,
                              (const char*)Al + (size_t)bm * 1024 };
    const char* Bparts[3] = { (const char*)Bh + (size_t)bn * 1024,
                              (const char*)Bl + (size_t)bn * 1024,
                              (const char*)Bh + (size_t)bn * 1024 };

    const int lr0 = tid >> 2;
    const int lc0 = (tid & 3) * 16;
    const int arow = (lane & 7) + ((lane >> 3) & 1) * 8;
    const int asel = lane >> 4;
    const int brow = ((lane >> 4) & 1) * 8 + (lane & 7);
    const int bsel = (lane >> 3) & 1;
    const uint32_t a_lane = (uint32_t)(warp_m * 64 + arow) * ROWB;
    const uint32_t b_lane = (uint32_t)(warp_n * 32 + brow) * ROWB;

    float acc[4][4][4];
#pragma unroll
    for (int i = 0; i < 4; i++)
#pragma unroll
        for (int j = 0; j < 4; j++)
#pragma unroll
            for (int u = 0; u < 4; u++) acc[i][j][u] = 0.0f;

    auto load_stage = [&](int s, int buf) {
        const int p = s >> 4;
        const int ko = (s & 15) * 64;
        const uint32_t ab = sb + buf * (2 * TILEB);
        const uint32_t bb = ab + TILEB;
        const char* As = Aparts[p] + ko;
        const char* Bs = Bparts[p] + ko;
#pragma unroll
        for (int i = 0; i < 2; i++) {
            const int r = lr0 + i * 64;
            CP16(ab + r * ROWB + lc0, As + (size_t)r * 1024 + lc0);
            CP16(bb + r * ROWB + lc0, Bs + (size_t)r * 1024 + lc0);
        }
    };

    load_stage(0, 0); CP_COMMIT();
    load_stage(1, 1); CP_COMMIT();

    int buf = 0;
    for (int s = 0; s < KSTAGES; s++) {
        if (s + 2 < KSTAGES) { CP_WAIT1(); } else { CP_WAIT0(); }
        __syncthreads();
        if (s + 2 < KSTAGES) {
            int nb = buf + 2; if (nb >= NSTAGE) nb -= NSTAGE;
            load_stage(s + 2, nb);
            CP_COMMIT();
        }
        const uint32_t ab = sb + buf * (2 * TILEB);
        const uint32_t bb = ab + TILEB;
#pragma unroll
        for (int kh = 0; kh < 2; kh++) {
            uint32_t af[4][4], bf[2][4];
            const uint32_t kadd = kh * 32;
#pragma unroll
            for (int m = 0; m < 4; m++)
                ldsm4(af[m], ab + a_lane + m * (16 * ROWB) + kadd + asel * 16);
#pragma unroll
            for (int n2 = 0; n2 < 2; n2++)
                ldsm4(bf[n2], bb + b_lane + n2 * (16 * ROWB) + kadd + bsel * 16);
#pragma unroll
            for (int m = 0; m < 4; m++)
#pragma unroll
                for (int n = 0; n < 4; n++)
                    mma16816(acc[m][n], af[m],
                             bf[n >> 1][(n & 1) * 2 + 0], bf[n >> 1][(n & 1) * 2 + 1]);
        }
        buf++; if (buf == NSTAGE) buf = 0;
    }

    const float RS = rsqrtf(1.0f + EPSV);
    const int lm = lane >> 2;
    const int ln2 = (lane & 3) * 2;
    const int row0 = bm + warp_m * 64;
    const int col0 = bn + warp_n * 32;

#pragma unroll
    for (int m = 0; m < 4; m++) {
#pragma unroll
        for (int n = 0; n < 4; n++) {
            const int gn = col0 + n * 8 + ln2;
            const int r_lo = row0 + m * 16 + lm;
            const int r_hi = r_lo + 8;
            float* c = acc[m][n];
            if (F32OUT) {
                if (gn < Nout) {
                    const float bz0 = bias[gn], bz1 = bias[gn + 1];
                    *(float2*)(Cf + (size_t)r_lo * Nout + gn) = make_float2(c[0] + bz0, c[1] + bz1);
                    *(float2*)(Cf + (size_t)r_hi * Nout + gn) = make_float2(c[2] + bz0, c[3] + bz1);
                }
            } else {
                const float bz0 = bias[gn], bz1 = bias[gn + 1];
                const float s0 = gamma[gn] * RS, s1 = gamma[gn + 1] * RS;
                const float e0 = beta[gn], e1 = beta[gn + 1];
                float v[4];
                v[0] = (c[0] + bz0) * s0 + e0; v[1] = (c[1] + bz1) * s1 + e1;
                v[2] = (c[2] + bz0) * s0 + e0; v[3] = (c[3] + bz1) * s1 + e1;
#pragma unroll
                for (int u = 0; u < 4; u++) {
                    if (EPI == 1) v[u] = fmaxf(v[u], 0.0f);
                    else v[u] = 0.5f * v[u] * (1.0f + erff(v[u] * 0.70710678118654752f));
                }
                if (EPI == 3) {
                    const size_t o0 = (size_t)r_lo * HH + gn;
                    const size_t o1 = (size_t)r_hi * HH + gn;
                    __nv_bfloat162 rh0 = *(const __nv_bfloat162*)(Rh + o0);
                    __nv_bfloat162 rl0 = *(const __nv_bfloat162*)(Rl + o0);
                    __nv_bfloat162 rh1 = *(const __nv_bfloat162*)(Rh + o1);
                    __nv_bfloat162 rl1 = *(const __nv_bfloat162*)(Rl + o1);
                    v[0] += __bfloat162float(rh0.x) + __bfloat162float(rl0.x);
                    v[1] += __bfloat162float(rh0.y) + __bfloat162float(rl0.y);
                    v[2] += __bfloat162float(rh1.x) + __bfloat162float(rl1.x);
                    v[3] += __bfloat162float(rh1.y) + __bfloat162float(rl1.y);
                }
                __nv_bfloat162 hp0, lp0, hp1, lp1;
                hp0.x = __float2bfloat16(v[0]); hp0.y = __float2bfloat16(v[1]);
                lp0.x = __float2bfloat16(v[0] - __bfloat162float(hp0.x));
                lp0.y = __float2bfloat16(v[1] - __bfloat162float(hp0.y));
                hp1.x = __float2bfloat16(v[2]); hp1.y = __float2bfloat16(v[3]);
                lp1.x = __float2bfloat16(v[2] - __bfloat162float(hp1.x));
                lp1.y = __float2bfloat16(v[3] - __bfloat162float(hp1.y));
                *(__nv_bfloat162*)(Ch + (size_t)r_lo * HH + gn) = hp0;
                *(__nv_bfloat162*)(Cl + (size_t)r_lo * HH + gn) = lp0;
                *(__nv_bfloat162*)(Ch + (size_t)r_hi * HH + gn) = hp1;
                *(__nv_bfloat162*)(Cl + (size_t)r_hi * HH + gn) = lp1;
            }
        }
    }
}

// ===========================================================================
// Fused fi/fs head + node reduction. 512 threads, 16 warps (4x4), 32x32 tiles.
// grid (60, 64). Partials pse/psx/psf[row][node][slice].
// ===========================================================================
__global__ __launch_bounds__(512, 1) void gemm_fifs(
    const __nv_bfloat16* __restrict__ Ah, const __nv_bfloat16* __restrict__ Al,
    const __nv_bfloat16* __restrict__ BiH, const __nv_bfloat16* __restrict__ BiL,
    const __nv_bfloat16* __restrict__ BsH, const __nv_bfloat16* __restrict__ BsL,
    const float* __restrict__ x,
    const float* __restrict__ b_fi, const float* __restrict__ b_fs,
    float* __restrict__ pse, float* __restrict__ psx, float* __restrict__ psf)
{
    extern __shared__ char dsm[];
    const uint32_t sb = smem_u32(dsm);

    const int tid = threadIdx.x;
    const int lane = tid & 31;
    const int wid = tid >> 5;
    const int warp_m = wid >> 2;     // 0..3 (32-row slice)
    const int warp_n = wid & 3;      // 0..3 (32-col slice)
    const int ct = blockIdx.x;       // col tile 0..59
    const int bm = blockIdx.y * 128;
    const int bn = ct * 128;
    const int node = ct >> 2;
    const int slice = (ct & 3) * 4 + warp_n;
    const int xbase = (ct & 3) * 128 + warp_n * 32;

    const char* Aparts[3] = { (const char*)Ah + (size_t)bm * 1024,
                              (const char*)Ah + (size_t)bm * 1024,
                              (const char*)Al + (size_t)bm * 1024 };
    const char* BiP[3] = { (const char*)BiH + (size_t)bn * 1024,
                           (const char*)BiL + (size_t)bn * 1024,
                           (const char*)BiH + (size_t)bn * 1024 };
    const char* BsP[3] = { (const char*)BsH + (size_t)bn * 1024,
                           (const char*)BsL + (size_t)bn * 1024,
                           (const char*)BsH + (size_t)bn * 1024 };

    // loader: 512 threads -> exactly 1 chunk per tile
    const int lr0 = tid >> 2;            // 0..127
    const int lc0 = (tid & 3) * 16;
    const int arow = (lane & 7) + ((lane >> 3) & 1) * 8;
    const int asel = lane >> 4;
    const int brow = ((lane >> 4) & 1) * 8 + (lane & 7);
    const int bsel = (lane >> 3) & 1;
    const uint32_t a_lane = (uint32_t)(warp_m * 32 + arow) * ROWB;
    const uint32_t b_lane = (uint32_t)(warp_n * 32 + brow) * ROWB;

    float accI[2][4][4], accS[2][4][4];
#pragma unroll
    for (int i = 0; i < 2; i++)
#pragma unroll
        for (int j = 0; j < 4; j++)
#pragma unroll
            for (int u = 0; u < 4; u++) { accI[i][j][u] = 0.0f; accS[i][j][u] = 0.0f; }

    auto load_stage = [&](int s, int buf) {
        const int p = s >> 4;
        const int ko = (s & 15) * 64;
        const uint32_t ab = sb + buf * (3 * TILEB);
        const uint32_t ib = ab + TILEB;
        const uint32_t qb = ib + TILEB;
        CP16(ab + lr0 * ROWB + lc0, Aparts[p] + ko + (size_t)lr0 * 1024 + lc0);
        CP16(ib + lr0 * ROWB + lc0, BiP[p] + ko + (size_t)lr0 * 1024 + lc0);
        CP16(qb + lr0 * ROWB + lc0, BsP[p] + ko + (size_t)lr0 * 1024 + lc0);
    };

    load_stage(0, 0); CP_COMMIT();
    load_stage(1, 1); CP_COMMIT();

    int buf = 0;
    for (int s = 0; s < KSTAGES; s++) {
        if (s + 2 < KSTAGES) { CP_WAIT1(); } else { CP_WAIT0(); }
        __syncthreads();
        if (s + 2 < KSTAGES) {
            int nb = buf + 2; if (nb >= NSTAGE) nb -= NSTAGE;
            load_stage(s + 2, nb);
            CP_COMMIT();
        }
        const uint32_t ab = sb + buf * (3 * TILEB);
        const uint32_t ib = ab + TILEB;
        const uint32_t qb = ib + TILEB;
#pragma unroll
        for (int kh = 0; kh < 2; kh++) {
            uint32_t af[2][4], bi[2][4], bq[2][4];
            const uint32_t kadd = kh * 32;
#pragma unroll
            for (int m = 0; m < 2; m++)
                ldsm4(af[m], ab + a_lane + m * (16 * ROWB) + kadd + asel * 16);
#pragma unroll
            for (int n2 = 0; n2 < 2; n2++) {
                ldsm4(bi[n2], ib + b_lane + n2 * (16 * ROWB) + kadd + bsel * 16);
                ldsm4(bq[n2], qb + b_lane + n2 * (16 * ROWB) + kadd + bsel * 16);
            }
#pragma unroll
            for (int m = 0; m < 2; m++)
#pragma unroll
                for (int n = 0; n < 4; n++) {
                    mma16816(accI[m][n], af[m],
                             bi[n >> 1][(n & 1) * 2 + 0], bi[n >> 1][(n & 1) * 2 + 1]);
                    mma16816(accS[m][n], af[m],
                             bq[n >> 1][(n & 1) * 2 + 0], bq[n >> 1][(n & 1) * 2 + 1]);
                }
        }
        buf++; if (buf == NSTAGE) buf = 0;
    }

    // -------- fused reduction epilogue --------
    const int lm = lane >> 2;
    const int ln2 = (lane & 3) * 2;
    const int row0 = bm + warp_m * 32;
    const int col0 = bn + warp_n * 32;

    float se[4], sx[4], sf[4];
#pragma unroll
    for (int i = 0; i < 4; i++) { se[i] = 0.f; sx[i] = 0.f; sf[i] = 0.f; }

#pragma unroll
    for (int n = 0; n < 4; n++) {
        const int gn = col0 + n * 8 + ln2;
        const int xc = xbase + n * 8 + ln2;
        const float bi0 = b_fi[gn], bi1 = b_fi[gn + 1];
        const float bs0 = b_fs[gn], bs1 = b_fs[gn + 1];
#pragma unroll
        for (int m = 0; m < 2; m++) {
            const int r_lo = row0 + m * 16 + lm;
            const int r_hi = r_lo + 8;
            const float* ci = accI[m][n];
            const float* cs = accS[m][n];
            const float e0 = __expf(ci[0] + bi0);
            const float e1 = __expf(ci[1] + bi1);
            const float e2 = __expf(ci[2] + bi0);
            const float e3 = __expf(ci[3] + bi1);
            const float2 x0 = *(const float2*)(x + (size_t)r_lo * FF + xc);
            const float2 x1 = *(const float2*)(x + (size_t)r_hi * FF + xc);
            se[m * 2 + 0] += e0 + e1;
            se[m * 2 + 1] += e2 + e3;
            sx[m * 2 + 0] += e0 * x0.x + e1 * x0.y;
            sx[m * 2 + 1] += e2 * x1.x + e3 * x1.y;
            sf[m * 2 + 0] += e0 * (cs[0] + bs0) + e1 * (cs[1] + bs1);
            sf[m * 2 + 1] += e2 * (cs[2] + bs0) + e3 * (cs[3] + bs1);
        }
    }

#pragma unroll
    for (int i = 0; i < 4; i++) {
        se[i] += __shfl_xor_sync(0xffffffffu, se[i], 1);
        se[i] += __shfl_xor_sync(0xffffffffu, se[i], 2);
        sx[i] += __shfl_xor_sync(0xffffffffu, sx[i], 1);
        sx[i] += __shfl_xor_sync(0xffffffffu, sx[i], 2);
        sf[i] += __shfl_xor_sync(0xffffffffu, sf[i], 1);
        sf[i] += __shfl_xor_sync(0xffffffffu, sf[i], 2);
    }
    if ((lane & 3) == 0) {
#pragma unroll
        for (int i = 0; i < 4; i++) {
            const int row = row0 + (i >> 1) * 16 + lm + (i & 1) * 8;
            const size_t o = ((size_t)row * NNODES + node) * 16 + slice;
            pse[o] = se[i]; psx[o] = sx[i]; psf[o] = sf[i];
        }
    }
}

// ---------------- split x into bf16 hi/lo -----------------------------------
__global__ __launch_bounds__(256) void split_x_kernel(
    const float* __restrict__ x, __nv_bfloat16* __restrict__ xh,
    __nv_bfloat16* __restrict__ xl, int n)
{
    int i = blockIdx.x * blockDim.x + threadIdx.x;
    if (i < n) {
        float v = x[i];
        __nv_bfloat16 h = __float2bfloat16(v);
        xh[i] = h;
        xl[i] = __float2bfloat16(v - __bfloat162float(h));
    }
}

// ---------------- transpose + split weights: W[K,N] -> O[N,K] hi/lo ---------
__global__ __launch_bounds__(256) void wsplit_t_kernel(
    const float* __restrict__ W, __nv_bfloat16* __restrict__ Oh,
    __nv_bfloat16* __restrict__ Ol, int N)
{
    __shared__ float t[32][33];
    const int n0 = blockIdx.x * 32, k0 = blockIdx.y * 32;
    const int tx = threadIdx.x & 31, ty = threadIdx.x >> 5;
#pragma unroll
    for (int i = 0; i < 4; i++) {
        int k = k0 + ty + i * 8;
        int n = n0 + tx;
        t[ty + i * 8][tx] = (n < N) ? W[(size_t)k * N + n] : 0.0f;
    }
    __syncthreads();
#pragma unroll
    for (int i = 0; i < 4; i++) {
        int n = n0 + ty + i * 8;
        int k = k0 + tx;
        float v = t[tx][ty + i * 8];
        __nv_bfloat16 h = __float2bfloat16(v);
        Oh[(size_t)n * KDIM + k] = h;
        Ol[(size_t)n * KDIM + k] = __float2bfloat16(v - __bfloat162float(h));
    }
}

// ---------------- sd + tree combine -----------------------------------------
__global__ __launch_bounds__(128) void sd_combine_kernel(
    const float* __restrict__ pse, const float* __restrict__ psx,
    const float* __restrict__ psf, const float* __restrict__ lnc,
    float* __restrict__ out)
{
    __shared__ float s_sd[NNODES];
    __shared__ float coeff[NLEAVES];
    const int b = blockIdx.x;
    const int tid = threadIdx.x;

    if (tid < NNODES) {
        const size_t base = ((size_t)b * NNODES + tid) * 16;
        float se = 0.f, sx = 0.f, sf = 0.f;
#pragma unroll
        for (int s = 0; s < 16; s++) {
            se += pse[base + s]; sx += psx[base + s]; sf += psf[base + s];
        }
        const float z = (sx - sf) / se;
        s_sd[tid] = 1.0f / (1.0f + expf(-z));
    }
    __syncthreads();
    if (tid < NLEAVES) {
        const int l = tid;
        float p, c;
        p = s_sd[0];            c  = ((l >> 3) & 1) ? 1.0f - p : p;
        p = s_sd[1 + (l >> 3)]; c *= ((l >> 2) & 1) ? 1.0f - p : p;
        p = s_sd[3 + (l >> 2)]; c *= ((l >> 1) & 1) ? 1.0f - p : p;
        p = s_sd[7 + (l >> 1)]; c *= (l & 1)        ? 1.0f - p : p;
        coeff[l] = c;
    }
    __syncthreads();
    if (tid < CC) {
        const float* lp = lnc + (size_t)b * (NLEAVES * CC) + tid;
        float acc = 0.0f;
#pragma unroll
        for (int l = 0; l < NLEAVES; l++) acc += coeff[l] * lp[l * CC];
        out[b * CC + tid] = acc;
    }
}

// ===========================================================================
extern "C" void kernel_launch(void* const* d_in, const int* in_sizes, int n_in,
                              void* d_out, int out_size)
{
    const float* x    = (const float*)d_in[0];
    const float* w_in = (const float*)d_in[1];
    const float* b_in = (const float*)d_in[2];
    const float* g0   = (const float*)d_in[3];
    const float* be0  = (const float*)d_in[4];
    const float* bw1  = (const float*)d_in[5];
    const float* bb1  = (const float*)d_in[6];
    const float* bg1  = (const float*)d_in[7];
    const float* bbe1 = (const float*)d_in[8];
    const float* bw2  = (const float*)d_in[9];
    const float* bb2  = (const float*)d_in[10];
    const float* bg2  = (const float*)d_in[11];
    const float* bbe2 = (const float*)d_in[12];
    const float* w_fi = (const float*)d_in[13];
    const float* b_fi = (const float*)d_in[14];
    const float* w_fs = (const float*)d_in[15];
    const float* b_fs = (const float*)d_in[16];
    const float* w_lc = (const float*)d_in[17];
    const float* b_lc = (const float*)d_in[18];
    float* out = (float*)d_out;

    __nv_bfloat16 *xh, *xl, *p0h, *p0l, *p1h, *p1l, *pth, *ptl;
    __nv_bfloat16 *wih, *wil, *w1h, *w1l, *w2h, *w2l;
    __nv_bfloat16 *wfih, *wfil, *wfsh, *wfsl, *wlch, *wlcl;
    float *lc, *pse, *psx, *psf;
    cudaGetSymbolAddress((void**)&xh, g_xh);   cudaGetSymbolAddress((void**)&xl, g_xl);
    cudaGetSymbolAddress((void**)&p0h, g_p0h); cudaGetSymbolAddress((void**)&p0l, g_p0l);
    cudaGetSymbolAddress((void**)&p1h, g_p1h); cudaGetSymbolAddress((void**)&p1l, g_p1l);
    cudaGetSymbolAddress((void**)&pth, g_pth); cudaGetSymbolAddress((void**)&ptl, g_ptl);
    cudaGetSymbolAddress((void**)&wih, g_wih); cudaGetSymbolAddress((void**)&wil, g_wil);
    cudaGetSymbolAddress((void**)&w1h, g_w1h); cudaGetSymbolAddress((void**)&w1l, g_w1l);
    cudaGetSymbolAddress((void**)&w2h, g_w2h); cudaGetSymbolAddress((void**)&w2l, g_w2l);
    cudaGetSymbolAddress((void**)&wfih, g_wfih); cudaGetSymbolAddress((void**)&wfil, g_wfil);
    cudaGetSymbolAddress((void**)&wfsh, g_wfsh); cudaGetSymbolAddress((void**)&wfsl, g_wfsl);
    cudaGetSymbolAddress((void**)&wlch, g_wlch); cudaGetSymbolAddress((void**)&wlcl, g_wlcl);
    cudaGetSymbolAddress((void**)&lc, g_lc);
    cudaGetSymbolAddress((void**)&pse, g_pse);
    cudaGetSymbolAddress((void**)&psx, g_psx);
    cudaGetSymbolAddress((void**)&psf, g_psf);

    cudaFuncSetAttribute(gemm_mma<1, 0>, cudaFuncAttributeMaxDynamicSharedMemorySize, SMEM_G);
    cudaFuncSetAttribute(gemm_mma<2, 0>, cudaFuncAttributeMaxDynamicSharedMemorySize, SMEM_G);
    cudaFuncSetAttribute(gemm_mma<3, 0>, cudaFuncAttributeMaxDynamicSharedMemorySize, SMEM_G);
    cudaFuncSetAttribute(gemm_mma<0, 1>, cudaFuncAttributeMaxDynamicSharedMemorySize, SMEM_G);
    cudaFuncSetAttribute(gemm_fifs, cudaFuncAttributeMaxDynamicSharedMemorySize, SMEM_F);

    // ---- prep ----
    split_x_kernel<<<(BQ * FF + 255) / 256, 256>>>(x, xh, xl, BQ * FF);
    wsplit_t_kernel<<<dim3(HH / 32, KDIM / 32), 256>>>(w_in, wih, wil, HH);
    wsplit_t_kernel<<<dim3(HH / 32, KDIM / 32), 256>>>(bw1, w1h, w1l, HH);
    wsplit_t_kernel<<<dim3(HH / 32, KDIM / 32), 256>>>(bw1 + HH * HH, w1h + HH * HH, w1l + HH * HH, HH);
    wsplit_t_kernel<<<dim3(HH / 32, KDIM / 32), 256>>>(bw2, w2h, w2l, HH);
    wsplit_t_kernel<<<dim3(HH / 32, KDIM / 32), 256>>>(bw2 + HH * HH, w2h + HH * HH, w2l + HH * HH, HH);
    wsplit_t_kernel<<<dim3(NFI / 32, KDIM / 32), 256>>>(w_fi, wfih, wfil, NFI);
    wsplit_t_kernel<<<dim3(NFI / 32, KDIM / 32), 256>>>(w_fs, wfsh, wfsl, NFI);
    wsplit_t_kernel<<<dim3(NLCP / 32, KDIM / 32), 256>>>(w_lc, wlch, wlcl, NLC);

    const dim3 g512(HH / 128, BQ / 128);
    const dim3 gfi(NFI / 128, BQ / 128);
    const dim3 glc(NLCP / 128, BQ / 128);

    // trunk
    gemm_mma<1, 0><<<g512, 256, SMEM_G>>>(xh, xl, wih, wil,
        nullptr, p0h, p0l, HH, b_in, g0, be0, nullptr, nullptr);
    gemm_mma<2, 0><<<g512, 256, SMEM_G>>>(p0h, p0l, w1h, w1l,
        nullptr, pth, ptl, HH, bb1, bg1, bbe1, nullptr, nullptr);
    gemm_mma<3, 0><<<g512, 256, SMEM_G>>>(pth, ptl, w2h, w2l,
        nullptr, p1h, p1l, HH, bb2, bg2, bbe2, p0h, p0l);
    gemm_mma<2, 0><<<g512, 256, SMEM_G>>>(p1h, p1l, w1h + HH * HH, w1l + HH * HH,
        nullptr, pth, ptl, HH, bb1 + HH, bg1 + HH, bbe1 + HH, nullptr, nullptr);
    gemm_mma<3, 0><<<g512, 256, SMEM_G>>>(pth, ptl, w2h + HH * HH, w2l + HH * HH,
        nullptr, p0h, p0l, HH, bb2 + HH, bg2 + HH, bbe2 + HH, p1h, p1l);
    // fused heads + node reduction (h lives in p0)
    gemm_fifs<<<gfi, 512, SMEM_F>>>(p0h, p0l, wfih, wfil, wfsh, wfsl,
                                    x, b_fi, b_fs, pse, psx, psf);
    gemm_mma<0, 1><<<glc, 256, SMEM_G>>>(p0h, p0l, wlch, wlcl,
        lc, nullptr, nullptr, NLC, b_lc, nullptr, nullptr, nullptr, nullptr);
    // final reduction
    sd_combine_kernel<<<BQ, 128>>>(pse, psx, psf, lc, out);
}